// round 1
// baseline (speedup 1.0000x reference)
#include <cuda_runtime.h>
#include <math.h>

#define Bz  4
#define Tt  1024
#define Cc  1024
#define Hh  16
#define Dd  64
#define FFF 4096
#define MM  (Bz*Tt)           // 4096
#define NHEADS (Bz*Hh)        // 64

// ---------------- scratch (device globals; no allocation allowed) ----------------
__device__ float g_x   [MM*Cc];
__device__ float g_ln  [MM*Cc];
__device__ float g_wqkv_t[Cc*Hh*3*Dd];   // [C, 3072]
__device__ float g_cwq_t [Cc*Hh*Dd];     // [C, 1024]
__device__ float g_cwkv_t[Cc*Hh*2*Dd];   // [C, 2048]
__device__ float g_y   [MM*Hh*3*Dd];     // generic gemm out, up to [4096,3072]
__device__ float g_q   [NHEADS*Tt*Dd];
__device__ float g_k   [NHEADS*Tt*Dd];
__device__ float g_v   [NHEADS*Tt*Dd];
__device__ float g_s   [(size_t)NHEADS*Tt*Tt];  // 268 MB scores
__device__ float g_o   [NHEADS*Tt*Dd];
__device__ float g_m   [MM*Cc];
__device__ float g_ff  [MM*FFF];

// ---------------- weight head-pack:  W[H][C][J] -> Wt[C][H*J] ----------------
__global__ void pack_w_kernel(const float* __restrict__ W, float* __restrict__ Wt, int J) {
    int idx = blockIdx.x * blockDim.x + threadIdx.x;
    int total = Hh * Cc * J;
    if (idx >= total) return;
    int j = idx % J;
    int c = (idx / J) % Cc;
    int h = idx / (J * Cc);
    Wt[(size_t)c * (Hh * J) + h * J + j] = W[idx];
}

// ---------------- layernorm: one block per row of C=1024 ----------------
__global__ void __launch_bounds__(256) ln_kernel(const float* __restrict__ X,
                                                 const float* __restrict__ w,
                                                 const float* __restrict__ b,
                                                 float* __restrict__ Y) {
    int row = blockIdx.x;
    int tid = threadIdx.x;
    const float4* x4 = (const float4*)(X + (size_t)row * Cc);
    float4 v = x4[tid];
    float s  = v.x + v.y + v.z + v.w;
    float sq = v.x*v.x + v.y*v.y + v.z*v.z + v.w*v.w;
    #pragma unroll
    for (int o = 16; o > 0; o >>= 1) {
        s  += __shfl_xor_sync(0xffffffffu, s,  o);
        sq += __shfl_xor_sync(0xffffffffu, sq, o);
    }
    __shared__ float shs[8], shq[8];
    int wid = tid >> 5, lane = tid & 31;
    if (lane == 0) { shs[wid] = s; shq[wid] = sq; }
    __syncthreads();
    float tot = 0.f, totq = 0.f;
    #pragma unroll
    for (int i = 0; i < 8; i++) { tot += shs[i]; totq += shq[i]; }
    float mu   = tot / Cc;
    float var  = totq / Cc - mu * mu;
    float rstd = rsqrtf(var + 1e-5f);
    float4 wv = ((const float4*)w)[tid];
    float4 bv = ((const float4*)b)[tid];
    float4 o;
    o.x = (v.x - mu) * rstd * wv.x + bv.x;
    o.y = (v.y - mu) * rstd * wv.y + bv.y;
    o.z = (v.z - mu) * rstd * wv.z + bv.z;
    o.w = (v.w - mu) * rstd * wv.w + bv.w;
    ((float4*)(Y + (size_t)row * Cc))[tid] = o;
}

// ---------------- SGEMM 128x128x8, 256 threads, 8x8 per thread ----------------
// C = A[M,K] @ B[K,N] (+bias) (+relu) (+residual).  M%128==N%128==K%8==0.
__global__ void __launch_bounds__(256) sgemm_kernel(const float* __restrict__ A,
                                                    const float* __restrict__ Bm,
                                                    const float* __restrict__ bias,
                                                    const float* __restrict__ res,
                                                    float* __restrict__ Cm,
                                                    int M, int N, int K, int relu) {
    __shared__ float As[8][128];
    __shared__ float Bs[8][128];
    int tid = threadIdx.x;
    int tx = tid & 15, ty = tid >> 4;
    int m0 = blockIdx.y * 128, n0 = blockIdx.x * 128;

    int arow = tid >> 1;            // 0..127
    int aq   = (tid & 1) << 2;      // 0 or 4
    int brow = tid >> 5;            // 0..7
    int bcol = (tid & 31) << 2;     // 0..124
    const float* Aptr = A + (size_t)(m0 + arow) * K + aq;
    const float* Bptr = Bm + (size_t)brow * N + n0 + bcol;

    float acc[8][8];
    #pragma unroll
    for (int i = 0; i < 8; i++)
        #pragma unroll
        for (int j = 0; j < 8; j++) acc[i][j] = 0.f;

    for (int k0 = 0; k0 < K; k0 += 8) {
        float4 av = *(const float4*)(Aptr + k0);
        float4 bv = *(const float4*)(Bptr + (size_t)k0 * N);
        __syncthreads();
        As[aq + 0][arow] = av.x; As[aq + 1][arow] = av.y;
        As[aq + 2][arow] = av.z; As[aq + 3][arow] = av.w;
        *(float4*)&Bs[brow][bcol] = bv;
        __syncthreads();
        #pragma unroll
        for (int k = 0; k < 8; k++) {
            float4 a0 = *(float4*)&As[k][ty * 8];
            float4 a1 = *(float4*)&As[k][ty * 8 + 4];
            float4 b0 = *(float4*)&Bs[k][tx * 8];
            float4 b1 = *(float4*)&Bs[k][tx * 8 + 4];
            float ar[8] = {a0.x,a0.y,a0.z,a0.w,a1.x,a1.y,a1.z,a1.w};
            float br[8] = {b0.x,b0.y,b0.z,b0.w,b1.x,b1.y,b1.z,b1.w};
            #pragma unroll
            for (int i = 0; i < 8; i++)
                #pragma unroll
                for (int j = 0; j < 8; j++)
                    acc[i][j] += ar[i] * br[j];
        }
    }

    #pragma unroll
    for (int i = 0; i < 8; i++) {
        int m = m0 + ty * 8 + i;
        #pragma unroll
        for (int j = 0; j < 8; j++) {
            int n = n0 + tx * 8 + j;
            float v = acc[i][j];
            if (bias) v += bias[n];
            if (relu) v = fmaxf(v, 0.f);
            size_t idx = (size_t)m * N + n;
            if (res)  v += res[idx];
            Cm[idx] = v;
        }
    }
}

// ---------------- split packed heads: Y[M, H*pw] -> Out[B,H,T,64] at +off ----------------
__global__ void split_heads_kernel(const float* __restrict__ Y, float* __restrict__ Out,
                                   int pw, int off) {
    int idx = blockIdx.x * blockDim.x + threadIdx.x;
    if (idx >= NHEADS * Tt * Dd) return;
    int d = idx & 63;
    int t = (idx >> 6) & 1023;
    int h = (idx >> 16) & 15;
    int b = idx >> 20;
    Out[idx] = Y[(size_t)(b * Tt + t) * (Hh * pw) + h * pw + off + d];
}

// ---------------- merge heads: O[B,H,T,64] -> M[B,T,H*64] ----------------
__global__ void merge_heads_kernel(const float* __restrict__ O, float* __restrict__ Mg) {
    int idx = blockIdx.x * blockDim.x + threadIdx.x;
    if (idx >= MM * Cc) return;
    int d = idx & 63;
    int h = (idx >> 6) & 15;
    int t = (idx >> 10) & 1023;
    int b = idx >> 20;
    Mg[idx] = O[((size_t)(b * Hh + h) * Tt + t) * Dd + d];
}

// ---------------- attention scores: S[bh, t, s] = scale * Q.K^T (causal opt) ----------------
__global__ void __launch_bounds__(256) attn_scores_kernel(const float* __restrict__ Q,
                                                          const float* __restrict__ Kk,
                                                          float* __restrict__ S, int causal) {
    const float scale = 0.125f;   // D^-0.5
    int bh = blockIdx.z;
    int t0 = blockIdx.y * 64, s0 = blockIdx.x * 64;
    int tid = threadIdx.x, tx = tid & 15, ty = tid >> 4;
    float* Sb = S + (size_t)bh * Tt * Tt;

    if (causal && s0 > t0 + 63) {   // fully masked tile: fill and exit
        float4 mfill = make_float4(-1e30f, -1e30f, -1e30f, -1e30f);
        #pragma unroll
        for (int i = 0; i < 4; i++)
            *(float4*)&Sb[(size_t)(t0 + ty * 4 + i) * Tt + s0 + tx * 4] = mfill;
        return;
    }

    __shared__ float Qs[64][68];   // [d][t], padded for aligned float4
    __shared__ float Ks[64][68];   // [d][s]
    const float* Qb = Q + (size_t)bh * Tt * Dd;
    const float* Kb = Kk + (size_t)bh * Tt * Dd;
    {
        int r  = tid >> 2;          // 0..63
        int c0 = (tid & 3) * 16;    // 0,16,32,48
        #pragma unroll
        for (int q = 0; q < 4; q++) {
            float4 qv = *(const float4*)&Qb[(size_t)(t0 + r) * Dd + c0 + q * 4];
            Qs[c0 + q*4 + 0][r] = qv.x; Qs[c0 + q*4 + 1][r] = qv.y;
            Qs[c0 + q*4 + 2][r] = qv.z; Qs[c0 + q*4 + 3][r] = qv.w;
            float4 kv = *(const float4*)&Kb[(size_t)(s0 + r) * Dd + c0 + q * 4];
            Ks[c0 + q*4 + 0][r] = kv.x; Ks[c0 + q*4 + 1][r] = kv.y;
            Ks[c0 + q*4 + 2][r] = kv.z; Ks[c0 + q*4 + 3][r] = kv.w;
        }
    }
    __syncthreads();

    float acc[4][4];
    #pragma unroll
    for (int i = 0; i < 4; i++)
        #pragma unroll
        for (int j = 0; j < 4; j++) acc[i][j] = 0.f;

    #pragma unroll
    for (int k = 0; k < 64; k++) {
        float4 a = *(float4*)&Qs[k][ty * 4];
        float4 b = *(float4*)&Ks[k][tx * 4];
        float ar[4] = {a.x, a.y, a.z, a.w};
        float br[4] = {b.x, b.y, b.z, b.w};
        #pragma unroll
        for (int i = 0; i < 4; i++)
            #pragma unroll
            for (int j = 0; j < 4; j++)
                acc[i][j] += ar[i] * br[j];
    }

    #pragma unroll
    for (int i = 0; i < 4; i++) {
        int t = t0 + ty * 4 + i;
        int s = s0 + tx * 4;
        float4 o;
        o.x = (!causal || s + 0 <= t) ? acc[i][0] * scale : -1e30f;
        o.y = (!causal || s + 1 <= t) ? acc[i][1] * scale : -1e30f;
        o.z = (!causal || s + 2 <= t) ? acc[i][2] * scale : -1e30f;
        o.w = (!causal || s + 3 <= t) ? acc[i][3] * scale : -1e30f;
        *(float4*)&Sb[(size_t)t * Tt + s] = o;
    }
}

// ---------------- row softmax over T=1024 (in place) ----------------
__global__ void __launch_bounds__(256) softmax_kernel(float* __restrict__ S) {
    size_t row = blockIdx.x;
    float* p = S + row * Tt;
    int tid = threadIdx.x;
    float4 v = ((float4*)p)[tid];
    float mx = fmaxf(fmaxf(v.x, v.y), fmaxf(v.z, v.w));
    #pragma unroll
    for (int o = 16; o > 0; o >>= 1) mx = fmaxf(mx, __shfl_xor_sync(0xffffffffu, mx, o));
    __shared__ float red[8];
    int wid = tid >> 5, lane = tid & 31;
    if (lane == 0) red[wid] = mx;
    __syncthreads();
    float rowmax = -1e38f;
    #pragma unroll
    for (int i = 0; i < 8; i++) rowmax = fmaxf(rowmax, red[i]);
    __syncthreads();

    float4 e;
    e.x = __expf(v.x - rowmax); e.y = __expf(v.y - rowmax);
    e.z = __expf(v.z - rowmax); e.w = __expf(v.w - rowmax);
    float s = e.x + e.y + e.z + e.w;
    #pragma unroll
    for (int o = 16; o > 0; o >>= 1) s += __shfl_xor_sync(0xffffffffu, s, o);
    if (lane == 0) red[wid] = s;
    __syncthreads();
    float tot = 0.f;
    #pragma unroll
    for (int i = 0; i < 8; i++) tot += red[i];
    float inv = 1.f / tot;
    e.x *= inv; e.y *= inv; e.z *= inv; e.w *= inv;
    ((float4*)p)[tid] = e;
}

// ---------------- PV: O[bh,t,d] = sum_s P[bh,t,s] * V[bh,s,d] ----------------
__global__ void __launch_bounds__(256) attn_pv_kernel(const float* __restrict__ P,
                                                      const float* __restrict__ V,
                                                      float* __restrict__ O) {
    int bh = blockIdx.y, t0 = blockIdx.x * 64;
    int tid = threadIdx.x, tx = tid & 15, ty = tid >> 4;
    const float* Pb = P + (size_t)bh * Tt * Tt;
    const float* Vb = V + (size_t)bh * Tt * Dd;
    __shared__ float Ps[16][68];   // [s][t] transposed, padded
    __shared__ float Vs[16][64];   // [s][d]
    float acc[4][4];
    #pragma unroll
    for (int i = 0; i < 4; i++)
        #pragma unroll
        for (int j = 0; j < 4; j++) acc[i][j] = 0.f;

    int pr = tid >> 2;          // 0..63 (t)
    int pq = (tid & 3) * 4;     // 0,4,8,12 (s)
    int vr = tid >> 4;          // 0..15 (s)
    int vc = (tid & 15) * 4;    // 0..60 (d)

    for (int s0 = 0; s0 < Tt; s0 += 16) {
        float4 pv = *(const float4*)&Pb[(size_t)(t0 + pr) * Tt + s0 + pq];
        float4 vv = *(const float4*)&Vb[(size_t)(s0 + vr) * Dd + vc];
        __syncthreads();
        Ps[pq + 0][pr] = pv.x; Ps[pq + 1][pr] = pv.y;
        Ps[pq + 2][pr] = pv.z; Ps[pq + 3][pr] = pv.w;
        *(float4*)&Vs[vr][vc] = vv;
        __syncthreads();
        #pragma unroll
        for (int k = 0; k < 16; k++) {
            float4 a = *(float4*)&Ps[k][ty * 4];
            float4 b = *(float4*)&Vs[k][tx * 4];
            float ar[4] = {a.x, a.y, a.z, a.w};
            float br[4] = {b.x, b.y, b.z, b.w};
            #pragma unroll
            for (int i = 0; i < 4; i++)
                #pragma unroll
                for (int j = 0; j < 4; j++)
                    acc[i][j] += ar[i] * br[j];
        }
    }

    #pragma unroll
    for (int i = 0; i < 4; i++) {
        float4 o = make_float4(acc[i][0], acc[i][1], acc[i][2], acc[i][3]);
        *(float4*)&O[((size_t)bh * Tt + t0 + ty * 4 + i) * Dd + tx * 4] = o;
    }
}

// ======================================================================
extern "C" void kernel_launch(void* const* d_in, const int* in_sizes, int n_in,
                              void* d_out, int out_size) {
    const float* x       = (const float*)d_in[0];
    const float* enc     = (const float*)d_in[1];
    const float* w_qkv   = (const float*)d_in[2];
    const float* w_proj  = (const float*)d_in[3];
    const float* b_proj  = (const float*)d_in[4];
    const float* cw_q    = (const float*)d_in[5];
    const float* cw_kv   = (const float*)d_in[6];
    const float* cw_proj = (const float*)d_in[7];
    const float* cb_proj = (const float*)d_in[8];
    const float* ff1_w1  = (const float*)d_in[9];
    const float* ff1_b1  = (const float*)d_in[10];
    const float* ff1_w2  = (const float*)d_in[11];
    const float* ff1_b2  = (const float*)d_in[12];
    const float* ff2_w1  = (const float*)d_in[13];
    const float* ff2_b1  = (const float*)d_in[14];
    const float* ff2_w2  = (const float*)d_in[15];
    const float* ff2_b2  = (const float*)d_in[16];
    const float* ln1_w = (const float*)d_in[17]; const float* ln1_b = (const float*)d_in[18];
    const float* ln2_w = (const float*)d_in[19]; const float* ln2_b = (const float*)d_in[20];
    const float* ln3_w = (const float*)d_in[21]; const float* ln3_b = (const float*)d_in[22];
    const float* ln4_w = (const float*)d_in[23]; const float* ln4_b = (const float*)d_in[24];

    float *px, *pln, *pwqkv, *pcwq, *pcwkv, *py, *pq, *pk, *pv, *ps, *po, *pm, *pff;
    cudaGetSymbolAddress((void**)&px,    g_x);
    cudaGetSymbolAddress((void**)&pln,   g_ln);
    cudaGetSymbolAddress((void**)&pwqkv, g_wqkv_t);
    cudaGetSymbolAddress((void**)&pcwq,  g_cwq_t);
    cudaGetSymbolAddress((void**)&pcwkv, g_cwkv_t);
    cudaGetSymbolAddress((void**)&py,    g_y);
    cudaGetSymbolAddress((void**)&pq,    g_q);
    cudaGetSymbolAddress((void**)&pk,    g_k);
    cudaGetSymbolAddress((void**)&pv,    g_v);
    cudaGetSymbolAddress((void**)&ps,    g_s);
    cudaGetSymbolAddress((void**)&po,    g_o);
    cudaGetSymbolAddress((void**)&pm,    g_m);
    cudaGetSymbolAddress((void**)&pff,   g_ff);

    const int EL = NHEADS * Tt * Dd;           // 4,194,304
    const int ELG = (EL + 255) / 256;
    const int MCG = (MM * Cc + 255) / 256;

    // ---- weight packing + x copy ----
    pack_w_kernel<<<(Hh*Cc*192 + 255) / 256, 256>>>(w_qkv, pwqkv, 192);
    pack_w_kernel<<<(Hh*Cc*64  + 255) / 256, 256>>>(cw_q,  pcwq,  64);
    pack_w_kernel<<<(Hh*Cc*128 + 255) / 256, 256>>>(cw_kv, pcwkv, 128);
    cudaMemcpyAsync(px, x, (size_t)MM * Cc * sizeof(float), cudaMemcpyDeviceToDevice, 0);

    // ---- 1) causal self-attention ----
    ln_kernel<<<MM, 256>>>(px, ln1_w, ln1_b, pln);
    sgemm_kernel<<<dim3(24, 32), 256>>>(pln, pwqkv, nullptr, nullptr, py, MM, 3072, Cc, 0);
    split_heads_kernel<<<ELG, 256>>>(py, pq, 192, 0);
    split_heads_kernel<<<ELG, 256>>>(py, pk, 192, 64);
    split_heads_kernel<<<ELG, 256>>>(py, pv, 192, 128);
    attn_scores_kernel<<<dim3(16, 16, NHEADS), 256>>>(pq, pk, ps, 1);
    softmax_kernel<<<NHEADS * Tt, 256>>>(ps);
    attn_pv_kernel<<<dim3(16, NHEADS), 256>>>(ps, pv, po);
    merge_heads_kernel<<<MCG, 256>>>(po, pm);
    sgemm_kernel<<<dim3(8, 32), 256>>>(pm, w_proj, b_proj, px, px, MM, Cc, Cc, 0);

    // ---- 2) feed-forward 1 ----
    ln_kernel<<<MM, 256>>>(px, ln2_w, ln2_b, pln);
    sgemm_kernel<<<dim3(32, 32), 256>>>(pln, ff1_w1, ff1_b1, nullptr, pff, MM, FFF, Cc, 1);
    sgemm_kernel<<<dim3(8, 32), 256>>>(pff, ff1_w2, ff1_b2, px, px, MM, Cc, FFF, 0);

    // ---- 3) cross-attention ----
    ln_kernel<<<MM, 256>>>(px, ln3_w, ln3_b, pln);
    sgemm_kernel<<<dim3(8, 32), 256>>>(pln, pcwq, nullptr, nullptr, py, MM, 1024, Cc, 0);
    split_heads_kernel<<<ELG, 256>>>(py, pq, 64, 0);
    float* py2 = py + (size_t)MM * 1024;
    sgemm_kernel<<<dim3(16, 32), 256>>>(enc, pcwkv, nullptr, nullptr, py2, MM, 2048, Cc, 0);
    split_heads_kernel<<<ELG, 256>>>(py2, pk, 128, 0);
    split_heads_kernel<<<ELG, 256>>>(py2, pv, 128, 64);
    attn_scores_kernel<<<dim3(16, 16, NHEADS), 256>>>(pq, pk, ps, 0);
    softmax_kernel<<<NHEADS * Tt, 256>>>(ps);
    attn_pv_kernel<<<dim3(16, NHEADS), 256>>>(ps, pv, po);
    merge_heads_kernel<<<MCG, 256>>>(po, pm);
    sgemm_kernel<<<dim3(8, 32), 256>>>(pm, cw_proj, cb_proj, px, px, MM, Cc, Cc, 0);

    // ---- 4) feed-forward 2 (final output -> d_out) ----
    ln_kernel<<<MM, 256>>>(px, ln4_w, ln4_b, pln);
    sgemm_kernel<<<dim3(32, 32), 256>>>(pln, ff2_w1, ff2_b1, nullptr, pff, MM, FFF, Cc, 1);
    sgemm_kernel<<<dim3(8, 32), 256>>>(pff, ff2_w2, ff2_b2, px, (float*)d_out, MM, Cc, FFF, 0);
}

// round 2
// speedup vs baseline: 3.5506x; 3.5506x over previous
#include <cuda_runtime.h>
#include <cuda_fp16.h>
#include <cstdint>
#include <math.h>

#define Bz  4
#define Tt  1024
#define Cc  1024
#define Hh  16
#define Dd  64
#define FFF 4096
#define MM  (Bz*Tt)           // 4096
#define NHEADS (Bz*Hh)        // 64

// ---------------- scratch (device globals) ----------------
__device__ float  g_x   [MM*Cc];                 // fp32 residual stream
__device__ float  g_s   [(size_t)NHEADS*Tt*Tt];  // fp32 scores (268MB)
__device__ __half h_p   [(size_t)NHEADS*Tt*Tt];  // fp16 probs (134MB)
__device__ __half h_ln  [MM*Cc];
__device__ __half h_enc [MM*Cc];
__device__ __half h_wqkv[Cc*Hh*3*Dd];
__device__ __half h_cwq [Cc*Hh*Dd];
__device__ __half h_cwkv[Cc*Hh*2*Dd];
__device__ __half h_wproj[Cc*Cc];
__device__ __half h_cwproj[Cc*Cc];
__device__ __half h_ff1w1[Cc*FFF];
__device__ __half h_ff1w2[FFF*Cc];
__device__ __half h_ff2w1[Cc*FFF];
__device__ __half h_ff2w2[FFF*Cc];
__device__ __half h_y   [MM*Hh*3*Dd];
__device__ __half h_q   [NHEADS*Tt*Dd];
__device__ __half h_k   [NHEADS*Tt*Dd];
__device__ __half h_v   [NHEADS*Tt*Dd];
__device__ __half h_m   [MM*Cc];
__device__ __half h_ff  [MM*FFF];

// ---------------- mma/ldmatrix helpers ----------------
__device__ __forceinline__ uint32_t smem_u32(const void* p) {
    return (uint32_t)__cvta_generic_to_shared(p);
}
__device__ __forceinline__ void ldsm4(uint32_t& r0, uint32_t& r1, uint32_t& r2, uint32_t& r3, uint32_t a) {
    asm volatile("ldmatrix.sync.aligned.m8n8.x4.shared.b16 {%0,%1,%2,%3}, [%4];"
                 : "=r"(r0), "=r"(r1), "=r"(r2), "=r"(r3) : "r"(a));
}
__device__ __forceinline__ void ldsm4t(uint32_t& r0, uint32_t& r1, uint32_t& r2, uint32_t& r3, uint32_t a) {
    asm volatile("ldmatrix.sync.aligned.m8n8.x4.trans.shared.b16 {%0,%1,%2,%3}, [%4];"
                 : "=r"(r0), "=r"(r1), "=r"(r2), "=r"(r3) : "r"(a));
}
__device__ __forceinline__ void mma16816(float* c, uint32_t a0, uint32_t a1, uint32_t a2, uint32_t a3,
                                         uint32_t b0, uint32_t b1) {
    asm volatile("mma.sync.aligned.m16n8k16.row.col.f32.f16.f16.f32 "
                 "{%0,%1,%2,%3},{%4,%5,%6,%7},{%8,%9},{%0,%1,%2,%3};"
                 : "+f"(c[0]), "+f"(c[1]), "+f"(c[2]), "+f"(c[3])
                 : "r"(a0), "r"(a1), "r"(a2), "r"(a3), "r"(b0), "r"(b1));
}

// ---------------- converts ----------------
__global__ void f2h_kernel(const float* __restrict__ src, __half* __restrict__ dst, int n4) {
    int i = blockIdx.x * blockDim.x + threadIdx.x;
    if (i >= n4) return;
    float4 v = ((const float4*)src)[i];
    __half2* o = (__half2*)dst + i * 2;
    o[0] = __floats2half2_rn(v.x, v.y);
    o[1] = __floats2half2_rn(v.z, v.w);
}
// W[H][C][J] -> Wt[C][H*J] fp16
__global__ void pack_w_kernel(const float* __restrict__ W, __half* __restrict__ Wt, int J) {
    int idx = blockIdx.x * blockDim.x + threadIdx.x;
    int total = Hh * Cc * J;
    if (idx >= total) return;
    int j = idx % J;
    int c = (idx / J) % Cc;
    int h = idx / (J * Cc);
    Wt[(size_t)c * (Hh * J) + h * J + j] = __float2half(W[idx]);
}

// ---------------- layernorm fp32 in -> fp16 out ----------------
__global__ void __launch_bounds__(256) ln_kernel(const float* __restrict__ X,
                                                 const float* __restrict__ w,
                                                 const float* __restrict__ b,
                                                 __half* __restrict__ Y) {
    int row = blockIdx.x;
    int tid = threadIdx.x;
    const float4* x4 = (const float4*)(X + (size_t)row * Cc);
    float4 v = x4[tid];
    float s  = v.x + v.y + v.z + v.w;
    float sq = v.x*v.x + v.y*v.y + v.z*v.z + v.w*v.w;
    #pragma unroll
    for (int o = 16; o > 0; o >>= 1) {
        s  += __shfl_xor_sync(0xffffffffu, s,  o);
        sq += __shfl_xor_sync(0xffffffffu, sq, o);
    }
    __shared__ float shs[8], shq[8];
    int wid = tid >> 5, lane = tid & 31;
    if (lane == 0) { shs[wid] = s; shq[wid] = sq; }
    __syncthreads();
    float tot = 0.f, totq = 0.f;
    #pragma unroll
    for (int i = 0; i < 8; i++) { tot += shs[i]; totq += shq[i]; }
    float mu   = tot / Cc;
    float rstd = rsqrtf(totq / Cc - mu * mu + 1e-5f);
    float4 wv = ((const float4*)w)[tid];
    float4 bv = ((const float4*)b)[tid];
    __half2* y2 = (__half2*)(Y + (size_t)row * Cc) + tid * 2;
    y2[0] = __floats2half2_rn((v.x - mu) * rstd * wv.x + bv.x, (v.y - mu) * rstd * wv.y + bv.y);
    y2[1] = __floats2half2_rn((v.z - mu) * rstd * wv.z + bv.z, (v.w - mu) * rstd * wv.w + bv.w);
}

// ---------------- fp16 tensor-core GEMM 128x128x32, 256 thr, 8 warps ----------------
// C = A[M,K]@B[K,N] (+bias)(+relu)(+res). outH!=null -> fp16 out, else fp32 outF.
__global__ void __launch_bounds__(256) hgemm_kernel(const __half* __restrict__ A,
                                                    const __half* __restrict__ B,
                                                    const float* __restrict__ bias,
                                                    const float* __restrict__ res,
                                                    float* __restrict__ outF,
                                                    __half* __restrict__ outH,
                                                    int M, int N, int K, int relu) {
    __shared__ __half As[128][40];
    __shared__ __half Bs[32][136];
    int tid = threadIdx.x, lane = tid & 31, warp = tid >> 5;
    int wm = warp >> 2, wn = warp & 3;
    int m0 = blockIdx.y * 128, n0 = blockIdx.x * 128;

    float acc[4][4][4] = {};

    for (int k0 = 0; k0 < K; k0 += 32) {
        uint4 av[2], bv[2];
        #pragma unroll
        for (int j = 0; j < 2; j++) {
            int idx = tid + j * 256;
            av[j] = *(const uint4*)(A + (size_t)(m0 + (idx >> 2)) * K + k0 + (idx & 3) * 8);
            bv[j] = *(const uint4*)(B + (size_t)(k0 + (idx >> 4)) * N + n0 + (idx & 15) * 8);
        }
        __syncthreads();
        #pragma unroll
        for (int j = 0; j < 2; j++) {
            int idx = tid + j * 256;
            *(uint4*)&As[idx >> 2][(idx & 3) * 8] = av[j];
            *(uint4*)&Bs[idx >> 4][(idx & 15) * 8] = bv[j];
        }
        __syncthreads();
        #pragma unroll
        for (int kk = 0; kk < 32; kk += 16) {
            uint32_t a[4][4];
            #pragma unroll
            for (int mi = 0; mi < 4; mi++)
                ldsm4(a[mi][0], a[mi][1], a[mi][2], a[mi][3],
                      smem_u32(&As[wm * 64 + mi * 16 + (lane & 15)][kk + (lane >> 4) * 8]));
            #pragma unroll
            for (int n2 = 0; n2 < 2; n2++) {
                uint32_t b0, b1, b2, b3;
                ldsm4t(b0, b1, b2, b3,
                       smem_u32(&Bs[kk + (lane & 15)][wn * 32 + n2 * 16 + (lane >> 4) * 8]));
                #pragma unroll
                for (int mi = 0; mi < 4; mi++) {
                    mma16816(acc[mi][n2 * 2],     a[mi][0], a[mi][1], a[mi][2], a[mi][3], b0, b1);
                    mma16816(acc[mi][n2 * 2 + 1], a[mi][0], a[mi][1], a[mi][2], a[mi][3], b2, b3);
                }
            }
        }
    }

    #pragma unroll
    for (int mi = 0; mi < 4; mi++) {
        #pragma unroll
        for (int ni = 0; ni < 4; ni++) {
            int col = n0 + wn * 32 + ni * 8 + (lane & 3) * 2;
            #pragma unroll
            for (int r = 0; r < 2; r++) {
                int row = m0 + wm * 64 + mi * 16 + (lane >> 2) + r * 8;
                float v0 = acc[mi][ni][r * 2], v1 = acc[mi][ni][r * 2 + 1];
                if (bias) { v0 += bias[col]; v1 += bias[col + 1]; }
                if (relu) { v0 = fmaxf(v0, 0.f); v1 = fmaxf(v1, 0.f); }
                size_t idx = (size_t)row * N + col;
                if (res) { v0 += res[idx]; v1 += res[idx + 1]; }
                if (outH) {
                    *(__half2*)&outH[idx] = __floats2half2_rn(v0, v1);
                } else {
                    *(float2*)&outF[idx] = make_float2(v0, v1);
                }
            }
        }
    }
}

// ---------------- split heads: Y[M, H*pw] -> Out[bh][t][64] fp16 ----------------
__global__ void split_heads_kernel(const __half* __restrict__ Y, __half* __restrict__ Out,
                                   int pw, int off) {
    int idx = blockIdx.x * blockDim.x + threadIdx.x;
    if (idx >= NHEADS * Tt * Dd) return;
    int d = idx & 63;
    int t = (idx >> 6) & 1023;
    int h = (idx >> 16) & 15;
    int b = idx >> 20;
    Out[idx] = Y[(size_t)(b * Tt + t) * (Hh * pw) + h * pw + off + d];
}

// ---------------- attention scores (tensor core): S fp32 = scale*Q.K^T ----------------
__global__ void __launch_bounds__(128) hattn_scores(const __half* __restrict__ Q,
                                                    const __half* __restrict__ Kk,
                                                    float* __restrict__ S, int causal) {
    int bh = blockIdx.z;
    int t0 = blockIdx.y * 64, s0 = blockIdx.x * 64;
    if (causal && s0 > t0) return;   // fully masked tile: never read downstream
    __shared__ __half Qs[64][72];
    __shared__ __half Ks[64][72];
    int tid = threadIdx.x, lane = tid & 31, w = tid >> 5;
    const __half* Qb = Q + (size_t)bh * Tt * Dd;
    const __half* Kb = Kk + (size_t)bh * Tt * Dd;
    #pragma unroll
    for (int j = 0; j < 4; j++) {
        int idx = tid + j * 128;
        int row = idx >> 3, col = (idx & 7) * 8;
        *(uint4*)&Qs[row][col] = *(const uint4*)(Qb + (size_t)(t0 + row) * Dd + col);
        *(uint4*)&Ks[row][col] = *(const uint4*)(Kb + (size_t)(s0 + row) * Dd + col);
    }
    __syncthreads();

    float acc[8][4] = {};
    #pragma unroll
    for (int kk = 0; kk < 64; kk += 16) {
        uint32_t a0, a1, a2, a3;
        ldsm4(a0, a1, a2, a3, smem_u32(&Qs[w * 16 + (lane & 15)][kk + (lane >> 4) * 8]));
        #pragma unroll
        for (int sg = 0; sg < 4; sg++) {
            int srow = sg * 16 + (lane & 7) + ((lane >> 4) << 3);
            int dcol = kk + ((lane >> 3) & 1) * 8;
            uint32_t b0, b1, b2, b3;
            ldsm4(b0, b1, b2, b3, smem_u32(&Ks[srow][dcol]));
            mma16816(acc[sg * 2],     a0, a1, a2, a3, b0, b1);
            mma16816(acc[sg * 2 + 1], a0, a1, a2, a3, b2, b3);
        }
    }

    const float scale = 0.125f;
    float* Sb = S + (size_t)bh * Tt * Tt;
    #pragma unroll
    for (int ni = 0; ni < 8; ni++) {
        int s = s0 + ni * 8 + (lane & 3) * 2;
        #pragma unroll
        for (int r = 0; r < 2; r++) {
            int t = t0 + w * 16 + (lane >> 2) + r * 8;
            float v0 = acc[ni][r * 2] * scale, v1 = acc[ni][r * 2 + 1] * scale;
            if (causal) {
                if (s > t)     v0 = -1e30f;
                if (s + 1 > t) v1 = -1e30f;
            }
            *(float2*)&Sb[(size_t)t * Tt + s] = make_float2(v0, v1);
        }
    }
}

// ---------------- softmax: fp32 S row -> fp16 P row (causal length-aware) ----------------
__global__ void __launch_bounds__(256) softmax_kernel(const float* __restrict__ S,
                                                      __half* __restrict__ P, int causal) {
    int row = blockIdx.x;                   // bh*1024 + t
    int t = row & (Tt - 1);
    int L4 = causal ? (((t >> 6) + 1) << 4) : (Tt >> 2);
    const float* p = S + (size_t)row * Tt;
    int tid = threadIdx.x;
    float4 v = make_float4(-3e38f, -3e38f, -3e38f, -3e38f);
    if (tid < L4) v = ((const float4*)p)[tid];
    float mx = fmaxf(fmaxf(v.x, v.y), fmaxf(v.z, v.w));
    #pragma unroll
    for (int o = 16; o > 0; o >>= 1) mx = fmaxf(mx, __shfl_xor_sync(0xffffffffu, mx, o));
    __shared__ float red[8];
    int wid = tid >> 5, lane = tid & 31;
    if (lane == 0) red[wid] = mx;
    __syncthreads();
    float rowmax = -3e38f;
    #pragma unroll
    for (int i = 0; i < 8; i++) rowmax = fmaxf(rowmax, red[i]);
    __syncthreads();
    float4 e;
    e.x = __expf(v.x - rowmax); e.y = __expf(v.y - rowmax);
    e.z = __expf(v.z - rowmax); e.w = __expf(v.w - rowmax);
    float s = e.x + e.y + e.z + e.w;
    #pragma unroll
    for (int o = 16; o > 0; o >>= 1) s += __shfl_xor_sync(0xffffffffu, s, o);
    if (lane == 0) red[wid] = s;
    __syncthreads();
    float tot = 0.f;
    #pragma unroll
    for (int i = 0; i < 8; i++) tot += red[i];
    float inv = 1.f / tot;
    if (tid < L4) {
        __half2* out = (__half2*)(P + (size_t)row * Tt) + tid * 2;
        out[0] = __floats2half2_rn(e.x * inv, e.y * inv);
        out[1] = __floats2half2_rn(e.z * inv, e.w * inv);
    }
}

// ---------------- PV (tensor core), writes merged [B,T,H*D] fp16 directly ----------------
__global__ void __launch_bounds__(128) hattn_pv(const __half* __restrict__ P,
                                                const __half* __restrict__ V,
                                                __half* __restrict__ Mg, int causal) {
    int bh = blockIdx.y, t0 = blockIdx.x * 64;
    int sEnd = causal ? (t0 + 64) : Tt;
    __shared__ __half Ps[64][40];
    __shared__ __half Vs[32][72];
    int tid = threadIdx.x, lane = tid & 31, w = tid >> 5;
    const __half* Pb = P + (size_t)bh * Tt * Tt;
    const __half* Vb = V + (size_t)bh * Tt * Dd;
    float acc[8][4] = {};

    for (int s0 = 0; s0 < sEnd; s0 += 32) {
        uint4 pv[2], vv[2];
        #pragma unroll
        for (int j = 0; j < 2; j++) {
            int idx = tid + j * 128;
            pv[j] = *(const uint4*)(Pb + (size_t)(t0 + (idx >> 2)) * Tt + s0 + (idx & 3) * 8);
            vv[j] = *(const uint4*)(Vb + (size_t)(s0 + (idx >> 3)) * Dd + (idx & 7) * 8);
        }
        __syncthreads();
        #pragma unroll
        for (int j = 0; j < 2; j++) {
            int idx = tid + j * 128;
            *(uint4*)&Ps[idx >> 2][(idx & 3) * 8] = pv[j];
            *(uint4*)&Vs[idx >> 3][(idx & 7) * 8] = vv[j];
        }
        __syncthreads();
        #pragma unroll
        for (int kk = 0; kk < 32; kk += 16) {
            uint32_t a0, a1, a2, a3;
            ldsm4(a0, a1, a2, a3, smem_u32(&Ps[w * 16 + (lane & 15)][kk + (lane >> 4) * 8]));
            #pragma unroll
            for (int n2 = 0; n2 < 4; n2++) {
                uint32_t b0, b1, b2, b3;
                ldsm4t(b0, b1, b2, b3, smem_u32(&Vs[kk + (lane & 15)][n2 * 16 + (lane >> 4) * 8]));
                mma16816(acc[n2 * 2],     a0, a1, a2, a3, b0, b1);
                mma16816(acc[n2 * 2 + 1], a0, a1, a2, a3, b2, b3);
            }
        }
    }

    int b = bh >> 4, h = bh & 15;
    #pragma unroll
    for (int ni = 0; ni < 8; ni++) {
        int d = ni * 8 + (lane & 3) * 2;
        #pragma unroll
        for (int r = 0; r < 2; r++) {
            int t = t0 + w * 16 + (lane >> 2) + r * 8;
            *(__half2*)&Mg[(size_t)(b * Tt + t) * Cc + h * Dd + d] =
                __floats2half2_rn(acc[ni][r * 2], acc[ni][r * 2 + 1]);
        }
    }
}

// ======================================================================
extern "C" void kernel_launch(void* const* d_in, const int* in_sizes, int n_in,
                              void* d_out, int out_size) {
    const float* x       = (const float*)d_in[0];
    const float* enc     = (const float*)d_in[1];
    const float* w_qkv   = (const float*)d_in[2];
    const float* w_proj  = (const float*)d_in[3];
    const float* b_proj  = (const float*)d_in[4];
    const float* cw_q    = (const float*)d_in[5];
    const float* cw_kv   = (const float*)d_in[6];
    const float* cw_proj = (const float*)d_in[7];
    const float* cb_proj = (const float*)d_in[8];
    const float* ff1_w1  = (const float*)d_in[9];
    const float* ff1_b1  = (const float*)d_in[10];
    const float* ff1_w2  = (const float*)d_in[11];
    const float* ff1_b2  = (const float*)d_in[12];
    const float* ff2_w1  = (const float*)d_in[13];
    const float* ff2_b1  = (const float*)d_in[14];
    const float* ff2_w2  = (const float*)d_in[15];
    const float* ff2_b2  = (const float*)d_in[16];
    const float* ln1_w = (const float*)d_in[17]; const float* ln1_b = (const float*)d_in[18];
    const float* ln2_w = (const float*)d_in[19]; const float* ln2_b = (const float*)d_in[20];
    const float* ln3_w = (const float*)d_in[21]; const float* ln3_b = (const float*)d_in[22];
    const float* ln4_w = (const float*)d_in[23]; const float* ln4_b = (const float*)d_in[24];

    float *px, *ps;
    __half *pln, *penc, *pwqkv, *pcwq, *pcwkv, *pwproj, *pcwproj;
    __half *pf11, *pf12, *pf21, *pf22;
    __half *py, *pq, *pk, *pv, *pp, *pm, *pff;
    cudaGetSymbolAddress((void**)&px,     g_x);
    cudaGetSymbolAddress((void**)&ps,     g_s);
    cudaGetSymbolAddress((void**)&pp,     h_p);
    cudaGetSymbolAddress((void**)&pln,    h_ln);
    cudaGetSymbolAddress((void**)&penc,   h_enc);
    cudaGetSymbolAddress((void**)&pwqkv,  h_wqkv);
    cudaGetSymbolAddress((void**)&pcwq,   h_cwq);
    cudaGetSymbolAddress((void**)&pcwkv,  h_cwkv);
    cudaGetSymbolAddress((void**)&pwproj, h_wproj);
    cudaGetSymbolAddress((void**)&pcwproj,h_cwproj);
    cudaGetSymbolAddress((void**)&pf11,   h_ff1w1);
    cudaGetSymbolAddress((void**)&pf12,   h_ff1w2);
    cudaGetSymbolAddress((void**)&pf21,   h_ff2w1);
    cudaGetSymbolAddress((void**)&pf22,   h_ff2w2);
    cudaGetSymbolAddress((void**)&py,     h_y);
    cudaGetSymbolAddress((void**)&pq,     h_q);
    cudaGetSymbolAddress((void**)&pk,     h_k);
    cudaGetSymbolAddress((void**)&pv,     h_v);
    cudaGetSymbolAddress((void**)&pm,     h_m);
    cudaGetSymbolAddress((void**)&pff,    h_ff);

    const int EL  = NHEADS * Tt * Dd;
    const int ELG = (EL + 255) / 256;
    auto cgrid = [](int n4) { return (n4 + 255) / 256; };

    // ---- weight/input converts ----
    pack_w_kernel<<<(Hh*Cc*192 + 255) / 256, 256>>>(w_qkv, pwqkv, 192);
    pack_w_kernel<<<(Hh*Cc*64  + 255) / 256, 256>>>(cw_q,  pcwq,  64);
    pack_w_kernel<<<(Hh*Cc*128 + 255) / 256, 256>>>(cw_kv, pcwkv, 128);
    f2h_kernel<<<cgrid(Cc*Cc/4), 256>>>(w_proj,  pwproj,  Cc*Cc/4);
    f2h_kernel<<<cgrid(Cc*Cc/4), 256>>>(cw_proj, pcwproj, Cc*Cc/4);
    f2h_kernel<<<cgrid(Cc*FFF/4), 256>>>(ff1_w1, pf11, Cc*FFF/4);
    f2h_kernel<<<cgrid(FFF*Cc/4), 256>>>(ff1_w2, pf12, FFF*Cc/4);
    f2h_kernel<<<cgrid(Cc*FFF/4), 256>>>(ff2_w1, pf21, Cc*FFF/4);
    f2h_kernel<<<cgrid(FFF*Cc/4), 256>>>(ff2_w2, pf22, FFF*Cc/4);
    f2h_kernel<<<cgrid(MM*Cc/4), 256>>>(enc, penc, MM*Cc/4);
    cudaMemcpyAsync(px, x, (size_t)MM * Cc * sizeof(float), cudaMemcpyDeviceToDevice, 0);

    // ---- 1) causal self-attention ----
    ln_kernel<<<MM, 256>>>(px, ln1_w, ln1_b, pln);
    hgemm_kernel<<<dim3(24, 32), 256>>>(pln, pwqkv, nullptr, nullptr, nullptr, py, MM, 3072, Cc, 0);
    split_heads_kernel<<<ELG, 256>>>(py, pq, 192, 0);
    split_heads_kernel<<<ELG, 256>>>(py, pk, 192, 64);
    split_heads_kernel<<<ELG, 256>>>(py, pv, 192, 128);
    hattn_scores<<<dim3(16, 16, NHEADS), 128>>>(pq, pk, ps, 1);
    softmax_kernel<<<NHEADS * Tt, 256>>>(ps, pp, 1);
    hattn_pv<<<dim3(16, NHEADS), 128>>>(pp, pv, pm, 1);
    hgemm_kernel<<<dim3(8, 32), 256>>>(pm, pwproj, b_proj, px, px, nullptr, MM, Cc, Cc, 0);

    // ---- 2) feed-forward 1 ----
    ln_kernel<<<MM, 256>>>(px, ln2_w, ln2_b, pln);
    hgemm_kernel<<<dim3(32, 32), 256>>>(pln, pf11, ff1_b1, nullptr, nullptr, pff, MM, FFF, Cc, 1);
    hgemm_kernel<<<dim3(8, 32), 256>>>(pff, pf12, ff1_b2, px, px, nullptr, MM, Cc, FFF, 0);

    // ---- 3) cross-attention ----
    ln_kernel<<<MM, 256>>>(px, ln3_w, ln3_b, pln);
    hgemm_kernel<<<dim3(8, 32), 256>>>(pln, pcwq, nullptr, nullptr, nullptr, py, MM, 1024, Cc, 0);
    split_heads_kernel<<<ELG, 256>>>(py, pq, 64, 0);
    __half* py2 = py + (size_t)MM * 1024;
    hgemm_kernel<<<dim3(16, 32), 256>>>(penc, pcwkv, nullptr, nullptr, nullptr, py2, MM, 2048, Cc, 0);
    split_heads_kernel<<<ELG, 256>>>(py2, pk, 128, 0);
    split_heads_kernel<<<ELG, 256>>>(py2, pv, 128, 64);
    hattn_scores<<<dim3(16, 16, NHEADS), 128>>>(pq, pk, ps, 0);
    softmax_kernel<<<NHEADS * Tt, 256>>>(ps, pp, 0);
    hattn_pv<<<dim3(16, NHEADS), 128>>>(pp, pv, pm, 0);
    hgemm_kernel<<<dim3(8, 32), 256>>>(pm, pcwproj, cb_proj, px, px, nullptr, MM, Cc, Cc, 0);

    // ---- 4) feed-forward 2 (final output -> d_out) ----
    ln_kernel<<<MM, 256>>>(px, ln4_w, ln4_b, pln);
    hgemm_kernel<<<dim3(32, 32), 256>>>(pln, pf21, ff2_b1, nullptr, nullptr, pff, MM, FFF, Cc, 1);
    hgemm_kernel<<<dim3(8, 32), 256>>>(pff, pf22, ff2_b2, px, (float*)d_out, nullptr, MM, Cc, FFF, 0);
}

// round 3
// speedup vs baseline: 5.3992x; 1.5207x over previous
#include <cuda_runtime.h>
#include <cuda_fp16.h>
#include <cstdint>
#include <math.h>

#define Bz  4
#define Tt  1024
#define Cc  1024
#define Hh  16
#define Dd  64
#define FFF 4096
#define MM  (Bz*Tt)           // 4096
#define NHEADS (Bz*Hh)        // 64

// ---------------- scratch (device globals) ----------------
__device__ float  g_x   [MM*Cc];                 // fp32 residual stream
__device__ __half h_ln  [MM*Cc];
__device__ __half h_enc [MM*Cc];
__device__ __half h_wqkv[Cc*Hh*3*Dd];
__device__ __half h_cwq [Cc*Hh*Dd];
__device__ __half h_cwkv[Cc*Hh*2*Dd];
__device__ __half h_wproj[Cc*Cc];
__device__ __half h_cwproj[Cc*Cc];
__device__ __half h_ff1w1[Cc*FFF];
__device__ __half h_ff1w2[FFF*Cc];
__device__ __half h_ff2w1[Cc*FFF];
__device__ __half h_ff2w2[FFF*Cc];
__device__ __half h_y   [MM*Hh*3*Dd];            // qkv / (crossq | crosskv)
__device__ __half h_m   [MM*Cc];                 // merged attention out
__device__ __half h_ff  [MM*FFF];

// ---------------- mma/ldmatrix/cp.async helpers ----------------
__device__ __forceinline__ uint32_t smem_u32(const void* p) {
    return (uint32_t)__cvta_generic_to_shared(p);
}
__device__ __forceinline__ void ldsm4(uint32_t& r0, uint32_t& r1, uint32_t& r2, uint32_t& r3, uint32_t a) {
    asm volatile("ldmatrix.sync.aligned.m8n8.x4.shared.b16 {%0,%1,%2,%3}, [%4];"
                 : "=r"(r0), "=r"(r1), "=r"(r2), "=r"(r3) : "r"(a));
}
__device__ __forceinline__ void ldsm4t(uint32_t& r0, uint32_t& r1, uint32_t& r2, uint32_t& r3, uint32_t a) {
    asm volatile("ldmatrix.sync.aligned.m8n8.x4.trans.shared.b16 {%0,%1,%2,%3}, [%4];"
                 : "=r"(r0), "=r"(r1), "=r"(r2), "=r"(r3) : "r"(a));
}
__device__ __forceinline__ void mma16816(float* c, uint32_t a0, uint32_t a1, uint32_t a2, uint32_t a3,
                                         uint32_t b0, uint32_t b1) {
    asm volatile("mma.sync.aligned.m16n8k16.row.col.f32.f16.f16.f32 "
                 "{%0,%1,%2,%3},{%4,%5,%6,%7},{%8,%9},{%0,%1,%2,%3};"
                 : "+f"(c[0]), "+f"(c[1]), "+f"(c[2]), "+f"(c[3])
                 : "r"(a0), "r"(a1), "r"(a2), "r"(a3), "r"(b0), "r"(b1));
}
__device__ __forceinline__ void cpa16(uint32_t dst, const void* src) {
    asm volatile("cp.async.cg.shared.global [%0], [%1], 16;" :: "r"(dst), "l"(src));
}
__device__ __forceinline__ void cpa8(uint32_t dst, const void* src) {
    asm volatile("cp.async.ca.shared.global [%0], [%1], 8;" :: "r"(dst), "l"(src));
}

// ---------------- converts ----------------
__global__ void f2h_kernel(const float* __restrict__ src, __half* __restrict__ dst, int n4) {
    int i = blockIdx.x * blockDim.x + threadIdx.x;
    if (i >= n4) return;
    float4 v = ((const float4*)src)[i];
    __half2* o = (__half2*)dst + i * 2;
    o[0] = __floats2half2_rn(v.x, v.y);
    o[1] = __floats2half2_rn(v.z, v.w);
}
// W[H][C][J] -> Wt[C][H*J] fp16, 8 elements per thread
__global__ void pack_w_kernel(const float* __restrict__ W, __half* __restrict__ Wt, int J) {
    int i = blockIdx.x * blockDim.x + threadIdx.x;
    int J8 = J >> 3;
    int total8 = Hh * Cc * J8;
    if (i >= total8) return;
    int j8 = i % J8;
    int c = (i / J8) % Cc;
    int h = i / (J8 * Cc);
    const float4* src = (const float4*)(W + (size_t)(h * Cc + c) * J + j8 * 8);
    float4 v0 = src[0], v1 = src[1];
    __half2 o[4];
    o[0] = __floats2half2_rn(v0.x, v0.y); o[1] = __floats2half2_rn(v0.z, v0.w);
    o[2] = __floats2half2_rn(v1.x, v1.y); o[3] = __floats2half2_rn(v1.z, v1.w);
    *(uint4*)(Wt + (size_t)c * (Hh * J) + h * J + j8 * 8) = *(uint4*)o;
}

// ---------------- layernorm fp32 in -> fp16 out ----------------
__global__ void __launch_bounds__(256) ln_kernel(const float* __restrict__ X,
                                                 const float* __restrict__ w,
                                                 const float* __restrict__ b,
                                                 __half* __restrict__ Y) {
    int row = blockIdx.x;
    int tid = threadIdx.x;
    const float4* x4 = (const float4*)(X + (size_t)row * Cc);
    float4 v = x4[tid];
    float s  = v.x + v.y + v.z + v.w;
    float sq = v.x*v.x + v.y*v.y + v.z*v.z + v.w*v.w;
    #pragma unroll
    for (int o = 16; o > 0; o >>= 1) {
        s  += __shfl_xor_sync(0xffffffffu, s,  o);
        sq += __shfl_xor_sync(0xffffffffu, sq, o);
    }
    __shared__ float shs[8], shq[8];
    int wid = tid >> 5, lane = tid & 31;
    if (lane == 0) { shs[wid] = s; shq[wid] = sq; }
    __syncthreads();
    float tot = 0.f, totq = 0.f;
    #pragma unroll
    for (int i = 0; i < 8; i++) { tot += shs[i]; totq += shq[i]; }
    float mu   = tot / Cc;
    float rstd = rsqrtf(totq / Cc - mu * mu + 1e-5f);
    float4 wv = ((const float4*)w)[tid];
    float4 bv = ((const float4*)b)[tid];
    __half2* y2 = (__half2*)(Y + (size_t)row * Cc) + tid * 2;
    y2[0] = __floats2half2_rn((v.x - mu) * rstd * wv.x + bv.x, (v.y - mu) * rstd * wv.y + bv.y);
    y2[1] = __floats2half2_rn((v.z - mu) * rstd * wv.z + bv.z, (v.w - mu) * rstd * wv.w + bv.w);
}

// ---------------- fp16 tensor-core GEMM, cp.async 2-stage pipelined ----------------
// C = A[M,K]@B[K,N] (+bias)(+relu)(+res). outH!=null -> fp16 out, else fp32 outF.
__global__ void __launch_bounds__(256) hgemm_kernel(const __half* __restrict__ A,
                                                    const __half* __restrict__ B,
                                                    const float* __restrict__ bias,
                                                    const float* __restrict__ res,
                                                    float* __restrict__ outF,
                                                    __half* __restrict__ outH,
                                                    int M, int N, int K, int relu) {
    __shared__ __half As[2][128][40];
    __shared__ __half Bs[2][32][136];
    int tid = threadIdx.x, lane = tid & 31, warp = tid >> 5;
    int wm = warp >> 2, wn = warp & 3;
    int m0 = blockIdx.y * 128, n0 = blockIdx.x * 128;

    float acc[4][4][4] = {};

    auto load_stage = [&](int k0, int st) {
        #pragma unroll
        for (int j = 0; j < 4; j++) {
            int idx = tid + j * 256;
            int row = idx >> 3, c = (idx & 7) * 4;
            cpa8(smem_u32(&As[st][row][c]), A + (size_t)(m0 + row) * K + k0 + c);
        }
        #pragma unroll
        for (int j = 0; j < 2; j++) {
            int idx = tid + j * 256;
            int row = idx >> 4, c = (idx & 15) * 8;
            cpa16(smem_u32(&Bs[st][row][c]), B + (size_t)(k0 + row) * N + n0 + c);
        }
        asm volatile("cp.async.commit_group;");
    };

    load_stage(0, 0);
    int nIter = K >> 5;
    for (int it = 0; it < nIter; it++) {
        asm volatile("cp.async.wait_group 0;" ::: "memory");
        __syncthreads();
        if (it + 1 < nIter) load_stage((it + 1) << 5, (it + 1) & 1);
        int st = it & 1;
        #pragma unroll
        for (int kk = 0; kk < 32; kk += 16) {
            uint32_t a[4][4];
            #pragma unroll
            for (int mi = 0; mi < 4; mi++)
                ldsm4(a[mi][0], a[mi][1], a[mi][2], a[mi][3],
                      smem_u32(&As[st][wm * 64 + mi * 16 + (lane & 15)][kk + (lane >> 4) * 8]));
            #pragma unroll
            for (int n2 = 0; n2 < 2; n2++) {
                uint32_t b0, b1, b2, b3;
                ldsm4t(b0, b1, b2, b3,
                       smem_u32(&Bs[st][kk + (lane & 15)][wn * 32 + n2 * 16 + (lane >> 4) * 8]));
                #pragma unroll
                for (int mi = 0; mi < 4; mi++) {
                    mma16816(acc[mi][n2 * 2],     a[mi][0], a[mi][1], a[mi][2], a[mi][3], b0, b1);
                    mma16816(acc[mi][n2 * 2 + 1], a[mi][0], a[mi][1], a[mi][2], a[mi][3], b2, b3);
                }
            }
        }
    }

    #pragma unroll
    for (int mi = 0; mi < 4; mi++) {
        #pragma unroll
        for (int ni = 0; ni < 4; ni++) {
            int col = n0 + wn * 32 + ni * 8 + (lane & 3) * 2;
            #pragma unroll
            for (int r = 0; r < 2; r++) {
                int row = m0 + wm * 64 + mi * 16 + (lane >> 2) + r * 8;
                float v0 = acc[mi][ni][r * 2], v1 = acc[mi][ni][r * 2 + 1];
                if (bias) { v0 += bias[col]; v1 += bias[col + 1]; }
                if (relu) { v0 = fmaxf(v0, 0.f); v1 = fmaxf(v1, 0.f); }
                size_t idx = (size_t)row * N + col;
                if (res) { v0 += res[idx]; v1 += res[idx + 1]; }
                if (outH) {
                    *(__half2*)&outH[idx] = __floats2half2_rn(v0, v1);
                } else {
                    *(float2*)&outF[idx] = make_float2(v0, v1);
                }
            }
        }
    }
}

// ---------------- fused flash attention ----------------
// Reads Q/K/V strided from packed GEMM outputs; writes merged [B,T,H*D] fp16.
// Q tile 128 rows (8 warps x 16), K/V tiles 64.
__global__ void __launch_bounds__(256) flash_kernel(const __half* __restrict__ Q,
                                                    const __half* __restrict__ Kp,
                                                    const __half* __restrict__ Vp,
                                                    __half* __restrict__ Mg,
                                                    int strideQ, int pitchQ,
                                                    int strideKV, int pitchKV, int causal) {
    __shared__ __half Qs[128][72];
    __shared__ __half Ks[64][72];
    __shared__ __half Vs[64][72];
    int tid = threadIdx.x, lane = tid & 31, w = tid >> 5;
    int bh = blockIdx.y, b = bh >> 4, h = bh & 15;
    int t0 = blockIdx.x * 128;
    const __half* Qb = Q  + (size_t)b * Tt * strideQ  + h * pitchQ;
    const __half* Kb = Kp + (size_t)b * Tt * strideKV + h * pitchKV;
    const __half* Vb = Vp + (size_t)b * Tt * strideKV + h * pitchKV;

    // load Q tile, pre-scaled by D^-0.5 (exact in fp16)
    const __half2 sc = __float2half2_rn(0.125f);
    #pragma unroll
    for (int j = 0; j < 4; j++) {
        int idx = tid + j * 256;
        int row = idx >> 3, col = (idx & 7) * 8;
        uint4 v = *(const uint4*)(Qb + (size_t)(t0 + row) * strideQ + col);
        __half2* h2 = (__half2*)&v;
        #pragma unroll
        for (int q = 0; q < 4; q++) h2[q] = __hmul2(h2[q], sc);
        *(uint4*)&Qs[row][col] = v;
    }
    __syncthreads();

    uint32_t qf[4][4];
    #pragma unroll
    for (int kk = 0; kk < 4; kk++)
        ldsm4(qf[kk][0], qf[kk][1], qf[kk][2], qf[kk][3],
              smem_u32(&Qs[w * 16 + (lane & 15)][kk * 16 + (lane >> 4) * 8]));

    float m_[2] = {-1e30f, -1e30f}, l_[2] = {0.f, 0.f};
    float acc[8][4] = {};

    int sEnd = causal ? (t0 + 128) : Tt;
    for (int s0 = 0; s0 < sEnd; s0 += 64) {
        __syncthreads();
        #pragma unroll
        for (int j = 0; j < 2; j++) {
            int idx = tid + j * 256;
            int row = idx >> 3, col = (idx & 7) * 8;
            *(uint4*)&Ks[row][col] = *(const uint4*)(Kb + (size_t)(s0 + row) * strideKV + col);
            *(uint4*)&Vs[row][col] = *(const uint4*)(Vb + (size_t)(s0 + row) * strideKV + col);
        }
        __syncthreads();

        // S = Q K^T  (16x64 per warp)
        float sacc[8][4] = {};
        #pragma unroll
        for (int kk = 0; kk < 4; kk++) {
            #pragma unroll
            for (int sg = 0; sg < 4; sg++) {
                uint32_t b0, b1, b2, b3;
                ldsm4(b0, b1, b2, b3,
                      smem_u32(&Ks[sg * 16 + (lane & 7) + ((lane >> 4) << 3)][kk * 16 + ((lane >> 3) & 1) * 8]));
                mma16816(sacc[sg * 2],     qf[kk][0], qf[kk][1], qf[kk][2], qf[kk][3], b0, b1);
                mma16816(sacc[sg * 2 + 1], qf[kk][0], qf[kk][1], qf[kk][2], qf[kk][3], b2, b3);
            }
        }

        // causal mask (only tiles touching the diagonal for this warp)
        if (causal && s0 + 63 > t0 + w * 16) {
            int tr0 = t0 + w * 16 + (lane >> 2);
            int tr1 = tr0 + 8;
            #pragma unroll
            for (int ni = 0; ni < 8; ni++) {
                int s = s0 + ni * 8 + (lane & 3) * 2;
                if (s > tr0)     sacc[ni][0] = -1e30f;
                if (s + 1 > tr0) sacc[ni][1] = -1e30f;
                if (s > tr1)     sacc[ni][2] = -1e30f;
                if (s + 1 > tr1) sacc[ni][3] = -1e30f;
            }
        }

        // online softmax update
        __half2 ph[8][2];
        #pragma unroll
        for (int r = 0; r < 2; r++) {
            float rm = -1e30f;
            #pragma unroll
            for (int ni = 0; ni < 8; ni++)
                rm = fmaxf(rm, fmaxf(sacc[ni][r * 2], sacc[ni][r * 2 + 1]));
            rm = fmaxf(rm, __shfl_xor_sync(0xffffffffu, rm, 1));
            rm = fmaxf(rm, __shfl_xor_sync(0xffffffffu, rm, 2));
            float mn  = fmaxf(m_[r], rm);
            float fac = __expf(m_[r] - mn);
            float ls = 0.f;
            #pragma unroll
            for (int ni = 0; ni < 8; ni++) {
                float e0 = __expf(sacc[ni][r * 2]     - mn);
                float e1 = __expf(sacc[ni][r * 2 + 1] - mn);
                ls += e0 + e1;
                ph[ni][r] = __floats2half2_rn(e0, e1);
            }
            ls += __shfl_xor_sync(0xffffffffu, ls, 1);
            ls += __shfl_xor_sync(0xffffffffu, ls, 2);
            l_[r] = l_[r] * fac + ls;
            m_[r] = mn;
            #pragma unroll
            for (int ni = 0; ni < 8; ni++) { acc[ni][r * 2] *= fac; acc[ni][r * 2 + 1] *= fac; }
        }

        // O += P V   (P fragments come straight from the S accumulator layout)
        #pragma unroll
        for (int kk = 0; kk < 4; kk++) {
            uint32_t a0 = *(uint32_t*)&ph[2 * kk][0];
            uint32_t a1 = *(uint32_t*)&ph[2 * kk][1];
            uint32_t a2 = *(uint32_t*)&ph[2 * kk + 1][0];
            uint32_t a3 = *(uint32_t*)&ph[2 * kk + 1][1];
            #pragma unroll
            for (int n2 = 0; n2 < 4; n2++) {
                uint32_t b0, b1, b2, b3;
                ldsm4t(b0, b1, b2, b3,
                       smem_u32(&Vs[kk * 16 + (lane & 15)][n2 * 16 + (lane >> 4) * 8]));
                mma16816(acc[n2 * 2],     a0, a1, a2, a3, b0, b1);
                mma16816(acc[n2 * 2 + 1], a0, a1, a2, a3, b2, b3);
            }
        }
    }

    float inv0 = 1.f / l_[0], inv1 = 1.f / l_[1];
    #pragma unroll
    for (int ni = 0; ni < 8; ni++) {
        int d = ni * 8 + (lane & 3) * 2;
        int t = t0 + w * 16 + (lane >> 2);
        *(__half2*)&Mg[(size_t)(b * Tt + t) * Cc + h * Dd + d] =
            __floats2half2_rn(acc[ni][0] * inv0, acc[ni][1] * inv0);
        *(__half2*)&Mg[(size_t)(b * Tt + t + 8) * Cc + h * Dd + d] =
            __floats2half2_rn(acc[ni][2] * inv1, acc[ni][3] * inv1);
    }
}

// ======================================================================
extern "C" void kernel_launch(void* const* d_in, const int* in_sizes, int n_in,
                              void* d_out, int out_size) {
    const float* x       = (const float*)d_in[0];
    const float* enc     = (const float*)d_in[1];
    const float* w_qkv   = (const float*)d_in[2];
    const float* w_proj  = (const float*)d_in[3];
    const float* b_proj  = (const float*)d_in[4];
    const float* cw_q    = (const float*)d_in[5];
    const float* cw_kv   = (const float*)d_in[6];
    const float* cw_proj = (const float*)d_in[7];
    const float* cb_proj = (const float*)d_in[8];
    const float* ff1_w1  = (const float*)d_in[9];
    const float* ff1_b1  = (const float*)d_in[10];
    const float* ff1_w2  = (const float*)d_in[11];
    const float* ff1_b2  = (const float*)d_in[12];
    const float* ff2_w1  = (const float*)d_in[13];
    const float* ff2_b1  = (const float*)d_in[14];
    const float* ff2_w2  = (const float*)d_in[15];
    const float* ff2_b2  = (const float*)d_in[16];
    const float* ln1_w = (const float*)d_in[17]; const float* ln1_b = (const float*)d_in[18];
    const float* ln2_w = (const float*)d_in[19]; const float* ln2_b = (const float*)d_in[20];
    const float* ln3_w = (const float*)d_in[21]; const float* ln3_b = (const float*)d_in[22];
    const float* ln4_w = (const float*)d_in[23]; const float* ln4_b = (const float*)d_in[24];

    float *px;
    __half *pln, *penc, *pwqkv, *pcwq, *pcwkv, *pwproj, *pcwproj;
    __half *pf11, *pf12, *pf21, *pf22;
    __half *py, *pm, *pff;
    cudaGetSymbolAddress((void**)&px,     g_x);
    cudaGetSymbolAddress((void**)&pln,    h_ln);
    cudaGetSymbolAddress((void**)&penc,   h_enc);
    cudaGetSymbolAddress((void**)&pwqkv,  h_wqkv);
    cudaGetSymbolAddress((void**)&pcwq,   h_cwq);
    cudaGetSymbolAddress((void**)&pcwkv,  h_cwkv);
    cudaGetSymbolAddress((void**)&pwproj, h_wproj);
    cudaGetSymbolAddress((void**)&pcwproj,h_cwproj);
    cudaGetSymbolAddress((void**)&pf11,   h_ff1w1);
    cudaGetSymbolAddress((void**)&pf12,   h_ff1w2);
    cudaGetSymbolAddress((void**)&pf21,   h_ff2w1);
    cudaGetSymbolAddress((void**)&pf22,   h_ff2w2);
    cudaGetSymbolAddress((void**)&py,     h_y);
    cudaGetSymbolAddress((void**)&pm,     h_m);
    cudaGetSymbolAddress((void**)&pff,    h_ff);

    auto cgrid = [](int n) { return (n + 255) / 256; };

    // ---- weight/input converts ----
    pack_w_kernel<<<cgrid(Hh*Cc*192/8), 256>>>(w_qkv, pwqkv, 192);
    pack_w_kernel<<<cgrid(Hh*Cc*64/8),  256>>>(cw_q,  pcwq,  64);
    pack_w_kernel<<<cgrid(Hh*Cc*128/8), 256>>>(cw_kv, pcwkv, 128);
    f2h_kernel<<<cgrid(Cc*Cc/4),  256>>>(w_proj,  pwproj,  Cc*Cc/4);
    f2h_kernel<<<cgrid(Cc*Cc/4),  256>>>(cw_proj, pcwproj, Cc*Cc/4);
    f2h_kernel<<<cgrid(Cc*FFF/4), 256>>>(ff1_w1, pf11, Cc*FFF/4);
    f2h_kernel<<<cgrid(FFF*Cc/4), 256>>>(ff1_w2, pf12, FFF*Cc/4);
    f2h_kernel<<<cgrid(Cc*FFF/4), 256>>>(ff2_w1, pf21, Cc*FFF/4);
    f2h_kernel<<<cgrid(FFF*Cc/4), 256>>>(ff2_w2, pf22, FFF*Cc/4);
    f2h_kernel<<<cgrid(MM*Cc/4),  256>>>(enc, penc, MM*Cc/4);
    cudaMemcpyAsync(px, x, (size_t)MM * Cc * sizeof(float), cudaMemcpyDeviceToDevice, 0);

    // ---- 1) causal self-attention ----
    ln_kernel<<<MM, 256>>>(px, ln1_w, ln1_b, pln);
    hgemm_kernel<<<dim3(24, 32), 256>>>(pln, pwqkv, nullptr, nullptr, nullptr, py, MM, 3072, Cc, 0);
    // flash reads q/k/v packed: row stride 3072, head pitch 192, k at +64, v at +128
    flash_kernel<<<dim3(8, NHEADS), 256>>>(py, py + 64, py + 128, pm, 3072, 192, 3072, 192, 1);
    hgemm_kernel<<<dim3(8, 32), 256>>>(pm, pwproj, b_proj, px, px, nullptr, MM, Cc, Cc, 0);

    // ---- 2) feed-forward 1 ----
    ln_kernel<<<MM, 256>>>(px, ln2_w, ln2_b, pln);
    hgemm_kernel<<<dim3(32, 32), 256>>>(pln, pf11, ff1_b1, nullptr, nullptr, pff, MM, FFF, Cc, 1);
    hgemm_kernel<<<dim3(8, 32), 256>>>(pff, pf12, ff1_b2, px, px, nullptr, MM, Cc, FFF, 0);

    // ---- 3) cross-attention ----
    ln_kernel<<<MM, 256>>>(px, ln3_w, ln3_b, pln);
    hgemm_kernel<<<dim3(8, 32), 256>>>(pln, pcwq, nullptr, nullptr, nullptr, py, MM, 1024, Cc, 0);
    __half* py2 = py + (size_t)MM * 1024;
    hgemm_kernel<<<dim3(16, 32), 256>>>(penc, pcwkv, nullptr, nullptr, nullptr, py2, MM, 2048, Cc, 0);
    flash_kernel<<<dim3(8, NHEADS), 256>>>(py, py2, py2 + 64, pm, 1024, 64, 2048, 128, 0);
    hgemm_kernel<<<dim3(8, 32), 256>>>(pm, pcwproj, cb_proj, px, px, nullptr, MM, Cc, Cc, 0);

    // ---- 4) feed-forward 2 (final output -> d_out) ----
    ln_kernel<<<MM, 256>>>(px, ln4_w, ln4_b, pln);
    hgemm_kernel<<<dim3(32, 32), 256>>>(pln, pf21, ff2_b1, nullptr, nullptr, pff, MM, FFF, Cc, 1);
    hgemm_kernel<<<dim3(8, 32), 256>>>(pff, pf22, ff2_b2, px, (float*)d_out, nullptr, MM, Cc, FFF, 0);
}

// round 5
// speedup vs baseline: 7.1762x; 1.3291x over previous
#include <cuda_runtime.h>
#include <cuda_fp16.h>
#include <cstdint>
#include <math.h>

#define Bz  4
#define Tt  1024
#define Cc  1024
#define Hh  16
#define Dd  64
#define FFF 4096
#define MM  (Bz*Tt)           // 4096
#define NHEADS (Bz*Hh)        // 64

// ---------------- scratch (device globals) ----------------
__device__ float  g_x   [MM*Cc];                 // fp32 residual stream
__device__ __half h_ln  [MM*Cc];
__device__ __half h_enc [MM*Cc];
__device__ __half h_wqkv[Cc*Hh*3*Dd];
__device__ __half h_cwq [Cc*Hh*Dd];
__device__ __half h_cwkv[Cc*Hh*2*Dd];
__device__ __half h_wproj[Cc*Cc];
__device__ __half h_cwproj[Cc*Cc];
__device__ __half h_ff1w1[Cc*FFF];
__device__ __half h_ff1w2[FFF*Cc];
__device__ __half h_ff2w1[Cc*FFF];
__device__ __half h_ff2w2[FFF*Cc];
__device__ __half h_y   [MM*Hh*3*Dd];            // qkv / (crossq | crosskv)
__device__ __half h_m   [MM*Cc];                 // merged attention out
__device__ __half h_ff  [MM*FFF];

// ---------------- mma/ldmatrix/cp.async helpers ----------------
__device__ __forceinline__ uint32_t smem_u32(const void* p) {
    return (uint32_t)__cvta_generic_to_shared(p);
}
__device__ __forceinline__ void ldsm4(uint32_t& r0, uint32_t& r1, uint32_t& r2, uint32_t& r3, uint32_t a) {
    asm volatile("ldmatrix.sync.aligned.m8n8.x4.shared.b16 {%0,%1,%2,%3}, [%4];"
                 : "=r"(r0), "=r"(r1), "=r"(r2), "=r"(r3) : "r"(a));
}
__device__ __forceinline__ void ldsm4t(uint32_t& r0, uint32_t& r1, uint32_t& r2, uint32_t& r3, uint32_t a) {
    asm volatile("ldmatrix.sync.aligned.m8n8.x4.trans.shared.b16 {%0,%1,%2,%3}, [%4];"
                 : "=r"(r0), "=r"(r1), "=r"(r2), "=r"(r3) : "r"(a));
}
__device__ __forceinline__ void mma16816(float* c, uint32_t a0, uint32_t a1, uint32_t a2, uint32_t a3,
                                         uint32_t b0, uint32_t b1) {
    asm volatile("mma.sync.aligned.m16n8k16.row.col.f32.f16.f16.f32 "
                 "{%0,%1,%2,%3},{%4,%5,%6,%7},{%8,%9},{%0,%1,%2,%3};"
                 : "+f"(c[0]), "+f"(c[1]), "+f"(c[2]), "+f"(c[3])
                 : "r"(a0), "r"(a1), "r"(a2), "r"(a3), "r"(b0), "r"(b1));
}
__device__ __forceinline__ void cpa16(uint32_t dst, const void* src) {
    asm volatile("cp.async.cg.shared.global [%0], [%1], 16;" :: "r"(dst), "l"(src));
}
#define CP_COMMIT()  asm volatile("cp.async.commit_group;")
#define CP_WAIT(n)   asm volatile("cp.async.wait_group %0;" :: "n"(n) : "memory")

// ---------------- converts ----------------
__global__ void f2h_kernel(const float* __restrict__ src, __half* __restrict__ dst, int n4) {
    int i = blockIdx.x * blockDim.x + threadIdx.x;
    if (i >= n4) return;
    float4 v = ((const float4*)src)[i];
    __half2* o = (__half2*)dst + i * 2;
    o[0] = __floats2half2_rn(v.x, v.y);
    o[1] = __floats2half2_rn(v.z, v.w);
}
// W[H][C][J] -> Wt[C][H*J] fp16, 8 elements per thread
__global__ void pack_w_kernel(const float* __restrict__ W, __half* __restrict__ Wt, int J) {
    int i = blockIdx.x * blockDim.x + threadIdx.x;
    int J8 = J >> 3;
    int total8 = Hh * Cc * J8;
    if (i >= total8) return;
    int j8 = i % J8;
    int c = (i / J8) % Cc;
    int h = i / (J8 * Cc);
    const float4* src = (const float4*)(W + (size_t)(h * Cc + c) * J + j8 * 8);
    float4 v0 = src[0], v1 = src[1];
    __half2 o[4];
    o[0] = __floats2half2_rn(v0.x, v0.y); o[1] = __floats2half2_rn(v0.z, v0.w);
    o[2] = __floats2half2_rn(v1.x, v1.y); o[3] = __floats2half2_rn(v1.z, v1.w);
    *(uint4*)(Wt + (size_t)c * (Hh * J) + h * J + j8 * 8) = *(uint4*)o;
}

// ---------------- layernorm fp32 in -> fp16 out ----------------
__global__ void __launch_bounds__(256) ln_kernel(const float* __restrict__ X,
                                                 const float* __restrict__ w,
                                                 const float* __restrict__ b,
                                                 __half* __restrict__ Y) {
    int row = blockIdx.x;
    int tid = threadIdx.x;
    const float4* x4 = (const float4*)(X + (size_t)row * Cc);
    float4 v = x4[tid];
    float s  = v.x + v.y + v.z + v.w;
    float sq = v.x*v.x + v.y*v.y + v.z*v.z + v.w*v.w;
    #pragma unroll
    for (int o = 16; o > 0; o >>= 1) {
        s  += __shfl_xor_sync(0xffffffffu, s,  o);
        sq += __shfl_xor_sync(0xffffffffu, sq, o);
    }
    __shared__ float shs[8], shq[8];
    int wid = tid >> 5, lane = tid & 31;
    if (lane == 0) { shs[wid] = s; shq[wid] = sq; }
    __syncthreads();
    float tot = 0.f, totq = 0.f;
    #pragma unroll
    for (int i = 0; i < 8; i++) { tot += shs[i]; totq += shq[i]; }
    float mu   = tot / Cc;
    float rstd = rsqrtf(totq / Cc - mu * mu + 1e-5f);
    float4 wv = ((const float4*)w)[tid];
    float4 bv = ((const float4*)b)[tid];
    __half2* y2 = (__half2*)(Y + (size_t)row * Cc) + tid * 2;
    y2[0] = __floats2half2_rn((v.x - mu) * rstd * wv.x + bv.x, (v.y - mu) * rstd * wv.y + bv.y);
    y2[1] = __floats2half2_rn((v.z - mu) * rstd * wv.z + bv.z, (v.w - mu) * rstd * wv.w + bv.w);
}

// ---------------- fp16 tensor-core GEMM, 3-stage cp.async pipeline ----------------
// C = A[M,K]@B[K,N] (+bias)(+relu)(+res). outH!=null -> fp16 out, else fp32 outF.
#define HG_STAGES 3
#define HG_AS (128*40)
#define HG_BS (32*136)
#define HG_SMEM (HG_STAGES*(HG_AS+HG_BS)*2)   // 56832 bytes

__global__ void __launch_bounds__(256, 2) hgemm_kernel(const __half* __restrict__ A,
                                                       const __half* __restrict__ B,
                                                       const float* __restrict__ bias,
                                                       const float* __restrict__ res,
                                                       float* __restrict__ outF,
                                                       __half* __restrict__ outH,
                                                       int M, int N, int K, int relu) {
    extern __shared__ __half hsm[];
    __half (*As)[128][40] = (__half(*)[128][40])hsm;
    __half (*Bs)[32][136] = (__half(*)[32][136])(hsm + HG_STAGES * HG_AS);
    int tid = threadIdx.x, lane = tid & 31, warp = tid >> 5;
    int wm = warp >> 2, wn = warp & 3;
    int m0 = blockIdx.y * 128, n0 = blockIdx.x * 128;

    float acc[4][4][4] = {};

    auto load_stage = [&](int k0, int st) {
        #pragma unroll
        for (int j = 0; j < 2; j++) {
            int idx = tid + j * 256;
            int row = idx >> 2, c = (idx & 3) * 8;
            cpa16(smem_u32(&As[st][row][c]), A + (size_t)(m0 + row) * K + k0 + c);
        }
        #pragma unroll
        for (int j = 0; j < 2; j++) {
            int idx = tid + j * 256;
            int row = idx >> 4, c = (idx & 15) * 8;
            cpa16(smem_u32(&Bs[st][row][c]), B + (size_t)(k0 + row) * N + n0 + c);
        }
    };

    int nIter = K >> 5;
    load_stage(0, 0); CP_COMMIT();
    load_stage(32, 1); CP_COMMIT();

    for (int it = 0; it < nIter; it++) {
        if (it + 2 < nIter) load_stage((it + 2) << 5, (it + 2) % 3);
        CP_COMMIT();                 // always commit (may be empty) to keep group count aligned
        CP_WAIT(2);                  // oldest (stage it) complete
        __syncthreads();
        int st = it % 3;
        #pragma unroll
        for (int kk = 0; kk < 32; kk += 16) {
            uint32_t a[4][4];
            #pragma unroll
            for (int mi = 0; mi < 4; mi++)
                ldsm4(a[mi][0], a[mi][1], a[mi][2], a[mi][3],
                      smem_u32(&As[st][wm * 64 + mi * 16 + (lane & 15)][kk + (lane >> 4) * 8]));
            #pragma unroll
            for (int n2 = 0; n2 < 2; n2++) {
                uint32_t b0, b1, b2, b3;
                ldsm4t(b0, b1, b2, b3,
                       smem_u32(&Bs[st][kk + (lane & 15)][wn * 32 + n2 * 16 + (lane >> 4) * 8]));
                #pragma unroll
                for (int mi = 0; mi < 4; mi++) {
                    mma16816(acc[mi][n2 * 2],     a[mi][0], a[mi][1], a[mi][2], a[mi][3], b0, b1);
                    mma16816(acc[mi][n2 * 2 + 1], a[mi][0], a[mi][1], a[mi][2], a[mi][3], b2, b3);
                }
            }
        }
        __syncthreads();
    }

    #pragma unroll
    for (int mi = 0; mi < 4; mi++) {
        #pragma unroll
        for (int ni = 0; ni < 4; ni++) {
            int col = n0 + wn * 32 + ni * 8 + (lane & 3) * 2;
            #pragma unroll
            for (int r = 0; r < 2; r++) {
                int row = m0 + wm * 64 + mi * 16 + (lane >> 2) + r * 8;
                float v0 = acc[mi][ni][r * 2], v1 = acc[mi][ni][r * 2 + 1];
                if (bias) { v0 += bias[col]; v1 += bias[col + 1]; }
                if (relu) { v0 = fmaxf(v0, 0.f); v1 = fmaxf(v1, 0.f); }
                size_t idx = (size_t)row * N + col;
                if (res) { v0 += res[idx]; v1 += res[idx + 1]; }
                if (outH) {
                    *(__half2*)&outH[idx] = __floats2half2_rn(v0, v1);
                } else {
                    *(float2*)&outF[idx] = make_float2(v0, v1);
                }
            }
        }
    }
}

// ---------------- fused flash attention, 2-stage cp.async K/V pipeline ----------------
// Reads Q/K/V strided from packed GEMM outputs; writes merged [B,T,H*D] fp16.
#define FL_QS (128*72)
#define FL_KS (64*72)
#define FL_SMEM ((FL_QS + 4*FL_KS)*2)    // 55296 bytes

__global__ void __launch_bounds__(256, 2) flash_kernel(const __half* __restrict__ Q,
                                                       const __half* __restrict__ Kp,
                                                       const __half* __restrict__ Vp,
                                                       __half* __restrict__ Mg,
                                                       int strideQ, int pitchQ,
                                                       int strideKV, int pitchKV, int causal) {
    extern __shared__ __half fsm[];
    __half (*Qs)[72] = (__half(*)[72])fsm;
    __half (*Ks)[64][72] = (__half(*)[64][72])(fsm + FL_QS);
    __half (*Vs)[64][72] = (__half(*)[64][72])(fsm + FL_QS + 2 * FL_KS);
    int tid = threadIdx.x, lane = tid & 31, w = tid >> 5;
    int bh = blockIdx.y, b = bh >> 4, h = bh & 15;
    int t0 = blockIdx.x * 128;
    const __half* Qb = Q  + (size_t)b * Tt * strideQ  + h * pitchQ;
    const __half* Kb = Kp + (size_t)b * Tt * strideKV + h * pitchKV;
    const __half* Vb = Vp + (size_t)b * Tt * strideKV + h * pitchKV;

    auto load_kv = [&](int s0, int st) {
        #pragma unroll
        for (int j = 0; j < 2; j++) {
            int idx = tid + j * 256;
            int row = idx >> 3, col = (idx & 7) * 8;
            cpa16(smem_u32(&Ks[st][row][col]), Kb + (size_t)(s0 + row) * strideKV + col);
            cpa16(smem_u32(&Vs[st][row][col]), Vb + (size_t)(s0 + row) * strideKV + col);
        }
    };

    int sEnd = causal ? (t0 + 128) : Tt;
    int nT = sEnd >> 6;
    load_kv(0, 0); CP_COMMIT();

    // load Q tile, pre-scaled by D^-0.5 (exact in fp16)
    const __half2 sc = __float2half2_rn(0.125f);
    #pragma unroll
    for (int j = 0; j < 4; j++) {
        int idx = tid + j * 256;
        int row = idx >> 3, col = (idx & 7) * 8;
        uint4 v = *(const uint4*)(Qb + (size_t)(t0 + row) * strideQ + col);
        __half2* h2 = (__half2*)&v;
        #pragma unroll
        for (int q = 0; q < 4; q++) h2[q] = __hmul2(h2[q], sc);
        *(uint4*)&Qs[row][col] = v;
    }
    __syncthreads();

    uint32_t qf[4][4];
    #pragma unroll
    for (int kk = 0; kk < 4; kk++)
        ldsm4(qf[kk][0], qf[kk][1], qf[kk][2], qf[kk][3],
              smem_u32(&Qs[w * 16 + (lane & 15)][kk * 16 + (lane >> 4) * 8]));

    float m_[2] = {-1e30f, -1e30f}, l_[2] = {0.f, 0.f};
    float acc[8][4] = {};

    for (int i = 0; i < nT; i++) {
        if (i + 1 < nT) load_kv((i + 1) << 6, (i + 1) & 1);
        CP_COMMIT();
        CP_WAIT(1);
        __syncthreads();
        int st = i & 1;
        int s0 = i << 6;

        // S = Q K^T  (16x64 per warp)
        float sacc[8][4] = {};
        #pragma unroll
        for (int kk = 0; kk < 4; kk++) {
            #pragma unroll
            for (int sg = 0; sg < 4; sg++) {
                uint32_t b0, b1, b2, b3;
                ldsm4(b0, b1, b2, b3,
                      smem_u32(&Ks[st][sg * 16 + (lane & 7) + ((lane >> 4) << 3)][kk * 16 + ((lane >> 3) & 1) * 8]));
                mma16816(sacc[sg * 2],     qf[kk][0], qf[kk][1], qf[kk][2], qf[kk][3], b0, b1);
                mma16816(sacc[sg * 2 + 1], qf[kk][0], qf[kk][1], qf[kk][2], qf[kk][3], b2, b3);
            }
        }

        if (causal && s0 + 63 > t0 + w * 16) {
            int tr0 = t0 + w * 16 + (lane >> 2);
            int tr1 = tr0 + 8;
            #pragma unroll
            for (int ni = 0; ni < 8; ni++) {
                int s = s0 + ni * 8 + (lane & 3) * 2;
                if (s > tr0)     sacc[ni][0] = -1e30f;
                if (s + 1 > tr0) sacc[ni][1] = -1e30f;
                if (s > tr1)     sacc[ni][2] = -1e30f;
                if (s + 1 > tr1) sacc[ni][3] = -1e30f;
            }
        }

        // online softmax update
        __half2 ph[8][2];
        #pragma unroll
        for (int r = 0; r < 2; r++) {
            float rm = -1e30f;
            #pragma unroll
            for (int ni = 0; ni < 8; ni++)
                rm = fmaxf(rm, fmaxf(sacc[ni][r * 2], sacc[ni][r * 2 + 1]));
            rm = fmaxf(rm, __shfl_xor_sync(0xffffffffu, rm, 1));
            rm = fmaxf(rm, __shfl_xor_sync(0xffffffffu, rm, 2));
            float mn  = fmaxf(m_[r], rm);
            float fac = __expf(m_[r] - mn);
            float ls = 0.f;
            #pragma unroll
            for (int ni = 0; ni < 8; ni++) {
                float e0 = __expf(sacc[ni][r * 2]     - mn);
                float e1 = __expf(sacc[ni][r * 2 + 1] - mn);
                ls += e0 + e1;
                ph[ni][r] = __floats2half2_rn(e0, e1);
            }
            ls += __shfl_xor_sync(0xffffffffu, ls, 1);
            ls += __shfl_xor_sync(0xffffffffu, ls, 2);
            l_[r] = l_[r] * fac + ls;
            m_[r] = mn;
            #pragma unroll
            for (int ni = 0; ni < 8; ni++) { acc[ni][r * 2] *= fac; acc[ni][r * 2 + 1] *= fac; }
        }

        // O += P V   (P fragments come straight from the S accumulator layout)
        #pragma unroll
        for (int kk = 0; kk < 4; kk++) {
            uint32_t a0 = *(uint32_t*)&ph[2 * kk][0];
            uint32_t a1 = *(uint32_t*)&ph[2 * kk][1];
            uint32_t a2 = *(uint32_t*)&ph[2 * kk + 1][0];
            uint32_t a3 = *(uint32_t*)&ph[2 * kk + 1][1];
            #pragma unroll
            for (int n2 = 0; n2 < 4; n2++) {
                uint32_t b0, b1, b2, b3;
                ldsm4t(b0, b1, b2, b3,
                       smem_u32(&Vs[st][kk * 16 + (lane & 15)][n2 * 16 + (lane >> 4) * 8]));
                mma16816(acc[n2 * 2],     a0, a1, a2, a3, b0, b1);
                mma16816(acc[n2 * 2 + 1], a0, a1, a2, a3, b2, b3);
            }
        }
        __syncthreads();
    }

    float inv0 = 1.f / l_[0], inv1 = 1.f / l_[1];
    #pragma unroll
    for (int ni = 0; ni < 8; ni++) {
        int d = ni * 8 + (lane & 3) * 2;
        int t = t0 + w * 16 + (lane >> 2);
        *(__half2*)&Mg[(size_t)(b * Tt + t) * Cc + h * Dd + d] =
            __floats2half2_rn(acc[ni][0] * inv0, acc[ni][1] * inv0);
        *(__half2*)&Mg[(size_t)(b * Tt + t + 8) * Cc + h * Dd + d] =
            __floats2half2_rn(acc[ni][2] * inv1, acc[ni][3] * inv1);
    }
}

// ======================================================================
extern "C" void kernel_launch(void* const* d_in, const int* in_sizes, int n_in,
                              void* d_out, int out_size) {
    const float* x       = (const float*)d_in[0];
    const float* enc     = (const float*)d_in[1];
    const float* w_qkv   = (const float*)d_in[2];
    const float* w_proj  = (const float*)d_in[3];
    const float* b_proj  = (const float*)d_in[4];
    const float* cw_q    = (const float*)d_in[5];
    const float* cw_kv   = (const float*)d_in[6];
    const float* cw_proj = (const float*)d_in[7];
    const float* cb_proj = (const float*)d_in[8];
    const float* ff1_w1  = (const float*)d_in[9];
    const float* ff1_b1  = (const float*)d_in[10];
    const float* ff1_w2  = (const float*)d_in[11];
    const float* ff1_b2  = (const float*)d_in[12];
    const float* ff2_w1  = (const float*)d_in[13];
    const float* ff2_b1  = (const float*)d_in[14];
    const float* ff2_w2  = (const float*)d_in[15];
    const float* ff2_b2  = (const float*)d_in[16];
    const float* ln1_w = (const float*)d_in[17]; const float* ln1_b = (const float*)d_in[18];
    const float* ln2_w = (const float*)d_in[19]; const float* ln2_b = (const float*)d_in[20];
    const float* ln3_w = (const float*)d_in[21]; const float* ln3_b = (const float*)d_in[22];
    const float* ln4_w = (const float*)d_in[23]; const float* ln4_b = (const float*)d_in[24];

    float *px;
    __half *pln, *penc, *pwqkv, *pcwq, *pcwkv, *pwproj, *pcwproj;
    __half *pf11, *pf12, *pf21, *pf22;
    __half *py, *pm, *pff;
    cudaGetSymbolAddress((void**)&px,     g_x);
    cudaGetSymbolAddress((void**)&pln,    h_ln);
    cudaGetSymbolAddress((void**)&penc,   h_enc);
    cudaGetSymbolAddress((void**)&pwqkv,  h_wqkv);
    cudaGetSymbolAddress((void**)&pcwq,   h_cwq);
    cudaGetSymbolAddress((void**)&pcwkv,  h_cwkv);
    cudaGetSymbolAddress((void**)&pwproj, h_wproj);
    cudaGetSymbolAddress((void**)&pcwproj,h_cwproj);
    cudaGetSymbolAddress((void**)&pf11,   h_ff1w1);
    cudaGetSymbolAddress((void**)&pf12,   h_ff1w2);
    cudaGetSymbolAddress((void**)&pf21,   h_ff2w1);
    cudaGetSymbolAddress((void**)&pf22,   h_ff2w2);
    cudaGetSymbolAddress((void**)&py,     h_y);
    cudaGetSymbolAddress((void**)&pm,     h_m);
    cudaGetSymbolAddress((void**)&pff,    h_ff);

    cudaFuncSetAttribute(hgemm_kernel, cudaFuncAttributeMaxDynamicSharedMemorySize, HG_SMEM);
    cudaFuncSetAttribute(flash_kernel, cudaFuncAttributeMaxDynamicSharedMemorySize, FL_SMEM);

    auto cgrid = [](int n) { return (n + 255) / 256; };

    // ---- weight/input converts ----
    pack_w_kernel<<<cgrid(Hh*Cc*192/8), 256>>>(w_qkv, pwqkv, 192);
    pack_w_kernel<<<cgrid(Hh*Cc*64/8),  256>>>(cw_q,  pcwq,  64);
    pack_w_kernel<<<cgrid(Hh*Cc*128/8), 256>>>(cw_kv, pcwkv, 128);
    f2h_kernel<<<cgrid(Cc*Cc/4),  256>>>(w_proj,  pwproj,  Cc*Cc/4);
    f2h_kernel<<<cgrid(Cc*Cc/4),  256>>>(cw_proj, pcwproj, Cc*Cc/4);
    f2h_kernel<<<cgrid(Cc*FFF/4), 256>>>(ff1_w1, pf11, Cc*FFF/4);
    f2h_kernel<<<cgrid(FFF*Cc/4), 256>>>(ff1_w2, pf12, FFF*Cc/4);
    f2h_kernel<<<cgrid(Cc*FFF/4), 256>>>(ff2_w1, pf21, Cc*FFF/4);
    f2h_kernel<<<cgrid(FFF*Cc/4), 256>>>(ff2_w2, pf22, FFF*Cc/4);
    f2h_kernel<<<cgrid(MM*Cc/4),  256>>>(enc, penc, MM*Cc/4);
    cudaMemcpyAsync(px, x, (size_t)MM * Cc * sizeof(float), cudaMemcpyDeviceToDevice, 0);

    // ---- 1) causal self-attention ----
    ln_kernel<<<MM, 256>>>(px, ln1_w, ln1_b, pln);
    hgemm_kernel<<<dim3(24, 32), 256, HG_SMEM>>>(pln, pwqkv, nullptr, nullptr, nullptr, py, MM, 3072, Cc, 0);
    flash_kernel<<<dim3(8, NHEADS), 256, FL_SMEM>>>(py, py + 64, py + 128, pm, 3072, 192, 3072, 192, 1);
    hgemm_kernel<<<dim3(8, 32), 256, HG_SMEM>>>(pm, pwproj, b_proj, px, px, nullptr, MM, Cc, Cc, 0);

    // ---- 2) feed-forward 1 ----
    ln_kernel<<<MM, 256>>>(px, ln2_w, ln2_b, pln);
    hgemm_kernel<<<dim3(32, 32), 256, HG_SMEM>>>(pln, pf11, ff1_b1, nullptr, nullptr, pff, MM, FFF, Cc, 1);
    hgemm_kernel<<<dim3(8, 32), 256, HG_SMEM>>>(pff, pf12, ff1_b2, px, px, nullptr, MM, Cc, FFF, 0);

    // ---- 3) cross-attention ----
    ln_kernel<<<MM, 256>>>(px, ln3_w, ln3_b, pln);
    hgemm_kernel<<<dim3(8, 32), 256, HG_SMEM>>>(pln, pcwq, nullptr, nullptr, nullptr, py, MM, 1024, Cc, 0);
    __half* py2 = py + (size_t)MM * 1024;
    hgemm_kernel<<<dim3(16, 32), 256, HG_SMEM>>>(penc, pcwkv, nullptr, nullptr, nullptr, py2, MM, 2048, Cc, 0);
    flash_kernel<<<dim3(8, NHEADS), 256, FL_SMEM>>>(py, py2, py2 + 64, pm, 1024, 64, 2048, 128, 0);
    hgemm_kernel<<<dim3(8, 32), 256, HG_SMEM>>>(pm, pcwproj, cb_proj, px, px, nullptr, MM, Cc, Cc, 0);

    // ---- 4) feed-forward 2 (final output -> d_out) ----
    ln_kernel<<<MM, 256>>>(px, ln4_w, ln4_b, pln);
    hgemm_kernel<<<dim3(32, 32), 256, HG_SMEM>>>(pln, pf21, ff2_b1, nullptr, nullptr, pff, MM, FFF, Cc, 1);
    hgemm_kernel<<<dim3(8, 32), 256, HG_SMEM>>>(pff, pf22, ff2_b2, px, (float*)d_out, nullptr, MM, Cc, FFF, 0);
}

// round 6
// speedup vs baseline: 7.9289x; 1.1049x over previous
#include <cuda_runtime.h>
#include <cuda_fp16.h>
#include <cstdint>
#include <math.h>

#define Bz  4
#define Tt  1024
#define Cc  1024
#define Hh  16
#define Dd  64
#define FFF 4096
#define MM  (Bz*Tt)           // 4096
#define NHEADS (Bz*Hh)        // 64

// ---------------- scratch (device globals) ----------------
__device__ float  g_x   [MM*Cc];                 // fp32 residual stream
__device__ __half h_ln  [MM*Cc];
__device__ __half h_enc [MM*Cc];
__device__ __half h_wqkv[Cc*Hh*3*Dd];
__device__ __half h_cwq [Cc*Hh*Dd];
__device__ __half h_cwkv[Cc*Hh*2*Dd];
__device__ __half h_wproj[Cc*Cc];
__device__ __half h_cwproj[Cc*Cc];
__device__ __half h_ff1w1[Cc*FFF];
__device__ __half h_ff1w2[FFF*Cc];
__device__ __half h_ff2w1[Cc*FFF];
__device__ __half h_ff2w2[FFF*Cc];
__device__ __half h_y   [MM*Hh*3*Dd];            // qkv / (crossq | crosskv)
__device__ __half h_m   [MM*Cc];                 // merged attention out
__device__ __half h_ff  [MM*FFF];

// ---------------- side stream for convert overlap (created once, pre-main) ----
static cudaStream_t g_s2;
static cudaEvent_t  g_ev1, g_ev2;
struct _StreamInit {
    _StreamInit() {
        cudaStreamCreateWithFlags(&g_s2, cudaStreamNonBlocking);
        cudaEventCreateWithFlags(&g_ev1, cudaEventDisableTiming);
        cudaEventCreateWithFlags(&g_ev2, cudaEventDisableTiming);
    }
};
static _StreamInit _stream_init_once;

// ---------------- mma/ldmatrix/cp.async helpers ----------------
__device__ __forceinline__ uint32_t smem_u32(const void* p) {
    return (uint32_t)__cvta_generic_to_shared(p);
}
__device__ __forceinline__ void ldsm4(uint32_t& r0, uint32_t& r1, uint32_t& r2, uint32_t& r3, uint32_t a) {
    asm volatile("ldmatrix.sync.aligned.m8n8.x4.shared.b16 {%0,%1,%2,%3}, [%4];"
                 : "=r"(r0), "=r"(r1), "=r"(r2), "=r"(r3) : "r"(a));
}
__device__ __forceinline__ void ldsm4t(uint32_t& r0, uint32_t& r1, uint32_t& r2, uint32_t& r3, uint32_t a) {
    asm volatile("ldmatrix.sync.aligned.m8n8.x4.trans.shared.b16 {%0,%1,%2,%3}, [%4];"
                 : "=r"(r0), "=r"(r1), "=r"(r2), "=r"(r3) : "r"(a));
}
__device__ __forceinline__ void mma16816(float* c, uint32_t a0, uint32_t a1, uint32_t a2, uint32_t a3,
                                         uint32_t b0, uint32_t b1) {
    asm volatile("mma.sync.aligned.m16n8k16.row.col.f32.f16.f16.f32 "
                 "{%0,%1,%2,%3},{%4,%5,%6,%7},{%8,%9},{%0,%1,%2,%3};"
                 : "+f"(c[0]), "+f"(c[1]), "+f"(c[2]), "+f"(c[3])
                 : "r"(a0), "r"(a1), "r"(a2), "r"(a3), "r"(b0), "r"(b1));
}
__device__ __forceinline__ void cpa16(uint32_t dst, const void* src) {
    asm volatile("cp.async.cg.shared.global [%0], [%1], 16;" :: "r"(dst), "l"(src));
}
#define CP_COMMIT()  asm volatile("cp.async.commit_group;")
#define CP_WAIT(n)   asm volatile("cp.async.wait_group %0;" :: "n"(n) : "memory")

// ---------------- converts ----------------
__global__ void f2h_kernel(const float* __restrict__ src, __half* __restrict__ dst, int n4) {
    int i = blockIdx.x * blockDim.x + threadIdx.x;
    if (i >= n4) return;
    float4 v = ((const float4*)src)[i];
    __half2* o = (__half2*)dst + i * 2;
    o[0] = __floats2half2_rn(v.x, v.y);
    o[1] = __floats2half2_rn(v.z, v.w);
}
// W[H][C][J] -> Wt[C][H*J] fp16, 8 elements per thread
__global__ void pack_w_kernel(const float* __restrict__ W, __half* __restrict__ Wt, int J) {
    int i = blockIdx.x * blockDim.x + threadIdx.x;
    int J8 = J >> 3;
    int total8 = Hh * Cc * J8;
    if (i >= total8) return;
    int j8 = i % J8;
    int c = (i / J8) % Cc;
    int h = i / (J8 * Cc);
    const float4* src = (const float4*)(W + (size_t)(h * Cc + c) * J + j8 * 8);
    float4 v0 = src[0], v1 = src[1];
    __half2 o[4];
    o[0] = __floats2half2_rn(v0.x, v0.y); o[1] = __floats2half2_rn(v0.z, v0.w);
    o[2] = __floats2half2_rn(v1.x, v1.y); o[3] = __floats2half2_rn(v1.z, v1.w);
    *(uint4*)(Wt + (size_t)c * (Hh * J) + h * J + j8 * 8) = *(uint4*)o;
}

// ---------------- layernorm fp32 in -> fp16 out ----------------
__global__ void __launch_bounds__(256) ln_kernel(const float* __restrict__ X,
                                                 const float* __restrict__ w,
                                                 const float* __restrict__ b,
                                                 __half* __restrict__ Y) {
    int row = blockIdx.x;
    int tid = threadIdx.x;
    const float4* x4 = (const float4*)(X + (size_t)row * Cc);
    float4 v = x4[tid];
    float s  = v.x + v.y + v.z + v.w;
    float sq = v.x*v.x + v.y*v.y + v.z*v.z + v.w*v.w;
    #pragma unroll
    for (int o = 16; o > 0; o >>= 1) {
        s  += __shfl_xor_sync(0xffffffffu, s,  o);
        sq += __shfl_xor_sync(0xffffffffu, sq, o);
    }
    __shared__ float shs[8], shq[8];
    int wid = tid >> 5, lane = tid & 31;
    if (lane == 0) { shs[wid] = s; shq[wid] = sq; }
    __syncthreads();
    float tot = 0.f, totq = 0.f;
    #pragma unroll
    for (int i = 0; i < 8; i++) { tot += shs[i]; totq += shq[i]; }
    float mu   = tot / Cc;
    float rstd = rsqrtf(totq / Cc - mu * mu + 1e-5f);
    float4 wv = ((const float4*)w)[tid];
    float4 bv = ((const float4*)b)[tid];
    __half2* y2 = (__half2*)(Y + (size_t)row * Cc) + tid * 2;
    y2[0] = __floats2half2_rn((v.x - mu) * rstd * wv.x + bv.x, (v.y - mu) * rstd * wv.y + bv.y);
    y2[1] = __floats2half2_rn((v.z - mu) * rstd * wv.z + bv.z, (v.w - mu) * rstd * wv.w + bv.w);
}

// ---------------- fp16 tensor-core GEMM, 4-stage cp.async ring, 1 barrier/iter ----
// C = A[M,K]@B[K,N] (+bias)(+relu)(+res). outH!=null -> fp16 out, else fp32 outF.
#define HG_STAGES 4
#define HG_AS (128*40)
#define HG_BS (32*136)
#define HG_SMEM (HG_STAGES*(HG_AS+HG_BS)*2)   // 75776 bytes

__global__ void __launch_bounds__(256, 2) hgemm_kernel(const __half* __restrict__ A,
                                                       const __half* __restrict__ B,
                                                       const float* __restrict__ bias,
                                                       const float* __restrict__ res,
                                                       float* __restrict__ outF,
                                                       __half* __restrict__ outH,
                                                       int M, int N, int K, int relu) {
    extern __shared__ __half hsm[];
    __half (*As)[128][40] = (__half(*)[128][40])hsm;
    __half (*Bs)[32][136] = (__half(*)[32][136])(hsm + HG_STAGES * HG_AS);
    int tid = threadIdx.x, lane = tid & 31, warp = tid >> 5;
    int wm = warp >> 2, wn = warp & 3;
    int m0 = blockIdx.y * 128, n0 = blockIdx.x * 128;

    float acc[4][4][4] = {};

    auto load_stage = [&](int k0, int st) {
        #pragma unroll
        for (int j = 0; j < 2; j++) {
            int idx = tid + j * 256;
            int row = idx >> 2, c = (idx & 3) * 8;
            cpa16(smem_u32(&As[st][row][c]), A + (size_t)(m0 + row) * K + k0 + c);
        }
        #pragma unroll
        for (int j = 0; j < 2; j++) {
            int idx = tid + j * 256;
            int row = idx >> 4, c = (idx & 15) * 8;
            cpa16(smem_u32(&Bs[st][row][c]), B + (size_t)(k0 + row) * N + n0 + c);
        }
    };

    int nIter = K >> 5;                 // chunks of 32; always >= 2 here
    load_stage(0, 0); CP_COMMIT();
    load_stage(32, 1); CP_COMMIT();

    for (int it = 0; it < nIter; it++) {
        if (it + 2 < nIter) load_stage((it + 2) << 5, (it + 2) & 3);
        CP_COMMIT();                 // uniform group count (may be empty)
        CP_WAIT(2);                  // chunk `it` resident
        __syncthreads();             // single barrier per iteration (safe: 4-stage ring)
        int st = it & 3;
        #pragma unroll
        for (int kk = 0; kk < 32; kk += 16) {
            uint32_t a[4][4];
            #pragma unroll
            for (int mi = 0; mi < 4; mi++)
                ldsm4(a[mi][0], a[mi][1], a[mi][2], a[mi][3],
                      smem_u32(&As[st][wm * 64 + mi * 16 + (lane & 15)][kk + (lane >> 4) * 8]));
            #pragma unroll
            for (int n2 = 0; n2 < 2; n2++) {
                uint32_t b0, b1, b2, b3;
                ldsm4t(b0, b1, b2, b3,
                       smem_u32(&Bs[st][kk + (lane & 15)][wn * 32 + n2 * 16 + (lane >> 4) * 8]));
                #pragma unroll
                for (int mi = 0; mi < 4; mi++) {
                    mma16816(acc[mi][n2 * 2],     a[mi][0], a[mi][1], a[mi][2], a[mi][3], b0, b1);
                    mma16816(acc[mi][n2 * 2 + 1], a[mi][0], a[mi][1], a[mi][2], a[mi][3], b2, b3);
                }
            }
        }
    }

    #pragma unroll
    for (int mi = 0; mi < 4; mi++) {
        #pragma unroll
        for (int ni = 0; ni < 4; ni++) {
            int col = n0 + wn * 32 + ni * 8 + (lane & 3) * 2;
            #pragma unroll
            for (int r = 0; r < 2; r++) {
                int row = m0 + wm * 64 + mi * 16 + (lane >> 2) + r * 8;
                float v0 = acc[mi][ni][r * 2], v1 = acc[mi][ni][r * 2 + 1];
                if (bias) { v0 += bias[col]; v1 += bias[col + 1]; }
                if (relu) { v0 = fmaxf(v0, 0.f); v1 = fmaxf(v1, 0.f); }
                size_t idx = (size_t)row * N + col;
                if (res) { v0 += res[idx]; v1 += res[idx + 1]; }
                if (outH) {
                    *(__half2*)&outH[idx] = __floats2half2_rn(v0, v1);
                } else {
                    *(float2*)&outF[idx] = make_float2(v0, v1);
                }
            }
        }
    }
}

// ---------------- fused flash attention, 4-stage cp.async K/V ring ----------------
// Reads Q/K/V strided from packed GEMM outputs; writes merged [B,T,H*D] fp16.
#define FL_QS (128*72)
#define FL_KS (64*72)
#define FL_SMEM ((FL_QS + 8*FL_KS)*2)    // 92160 bytes

__global__ void __launch_bounds__(256, 2) flash_kernel(const __half* __restrict__ Q,
                                                       const __half* __restrict__ Kp,
                                                       const __half* __restrict__ Vp,
                                                       __half* __restrict__ Mg,
                                                       int strideQ, int pitchQ,
                                                       int strideKV, int pitchKV, int causal) {
    extern __shared__ __half fsm[];
    __half (*Qs)[72] = (__half(*)[72])fsm;
    __half (*Ks)[64][72] = (__half(*)[64][72])(fsm + FL_QS);
    __half (*Vs)[64][72] = (__half(*)[64][72])(fsm + FL_QS + 4 * FL_KS);
    int tid = threadIdx.x, lane = tid & 31, w = tid >> 5;
    int bh = blockIdx.y, b = bh >> 4, h = bh & 15;
    int t0 = blockIdx.x * 128;
    const __half* Qb = Q  + (size_t)b * Tt * strideQ  + h * pitchQ;
    const __half* Kb = Kp + (size_t)b * Tt * strideKV + h * pitchKV;
    const __half* Vb = Vp + (size_t)b * Tt * strideKV + h * pitchKV;

    auto load_kv = [&](int s0, int st) {
        #pragma unroll
        for (int j = 0; j < 2; j++) {
            int idx = tid + j * 256;
            int row = idx >> 3, col = (idx & 7) * 8;
            cpa16(smem_u32(&Ks[st][row][col]), Kb + (size_t)(s0 + row) * strideKV + col);
            cpa16(smem_u32(&Vs[st][row][col]), Vb + (size_t)(s0 + row) * strideKV + col);
        }
    };

    int sEnd = causal ? (t0 + 128) : Tt;
    int nT = sEnd >> 6;                 // >= 2 always (t0 >= 0 -> causal nT >= 2)
    load_kv(0, 0); CP_COMMIT();
    if (nT > 1) load_kv(64, 1);
    CP_COMMIT();

    // load Q tile, pre-scaled by D^-0.5 (exact in fp16)
    const __half2 sc = __float2half2_rn(0.125f);
    #pragma unroll
    for (int j = 0; j < 4; j++) {
        int idx = tid + j * 256;
        int row = idx >> 3, col = (idx & 7) * 8;
        uint4 v = *(const uint4*)(Qb + (size_t)(t0 + row) * strideQ + col);
        __half2* h2 = (__half2*)&v;
        #pragma unroll
        for (int q = 0; q < 4; q++) h2[q] = __hmul2(h2[q], sc);
        *(uint4*)&Qs[row][col] = v;
    }
    __syncthreads();

    uint32_t qf[4][4];
    #pragma unroll
    for (int kk = 0; kk < 4; kk++)
        ldsm4(qf[kk][0], qf[kk][1], qf[kk][2], qf[kk][3],
              smem_u32(&Qs[w * 16 + (lane & 15)][kk * 16 + (lane >> 4) * 8]));

    float m_[2] = {-1e30f, -1e30f}, l_[2] = {0.f, 0.f};
    float acc[8][4] = {};

    for (int i = 0; i < nT; i++) {
        if (i + 2 < nT) load_kv((i + 2) << 6, (i + 2) & 3);
        CP_COMMIT();
        CP_WAIT(2);
        __syncthreads();             // single barrier per iteration (4-stage ring)
        int st = i & 3;
        int s0 = i << 6;

        // S = Q K^T  (16x64 per warp)
        float sacc[8][4] = {};
        #pragma unroll
        for (int kk = 0; kk < 4; kk++) {
            #pragma unroll
            for (int sg = 0; sg < 4; sg++) {
                uint32_t b0, b1, b2, b3;
                ldsm4(b0, b1, b2, b3,
                      smem_u32(&Ks[st][sg * 16 + (lane & 7) + ((lane >> 4) << 3)][kk * 16 + ((lane >> 3) & 1) * 8]));
                mma16816(sacc[sg * 2],     qf[kk][0], qf[kk][1], qf[kk][2], qf[kk][3], b0, b1);
                mma16816(sacc[sg * 2 + 1], qf[kk][0], qf[kk][1], qf[kk][2], qf[kk][3], b2, b3);
            }
        }

        if (causal && s0 + 63 > t0 + w * 16) {
            int tr0 = t0 + w * 16 + (lane >> 2);
            int tr1 = tr0 + 8;
            #pragma unroll
            for (int ni = 0; ni < 8; ni++) {
                int s = s0 + ni * 8 + (lane & 3) * 2;
                if (s > tr0)     sacc[ni][0] = -1e30f;
                if (s + 1 > tr0) sacc[ni][1] = -1e30f;
                if (s > tr1)     sacc[ni][2] = -1e30f;
                if (s + 1 > tr1) sacc[ni][3] = -1e30f;
            }
        }

        // online softmax update
        __half2 ph[8][2];
        #pragma unroll
        for (int r = 0; r < 2; r++) {
            float rm = -1e30f;
            #pragma unroll
            for (int ni = 0; ni < 8; ni++)
                rm = fmaxf(rm, fmaxf(sacc[ni][r * 2], sacc[ni][r * 2 + 1]));
            rm = fmaxf(rm, __shfl_xor_sync(0xffffffffu, rm, 1));
            rm = fmaxf(rm, __shfl_xor_sync(0xffffffffu, rm, 2));
            float mn  = fmaxf(m_[r], rm);
            float fac = __expf(m_[r] - mn);
            float ls = 0.f;
            #pragma unroll
            for (int ni = 0; ni < 8; ni++) {
                float e0 = __expf(sacc[ni][r * 2]     - mn);
                float e1 = __expf(sacc[ni][r * 2 + 1] - mn);
                ls += e0 + e1;
                ph[ni][r] = __floats2half2_rn(e0, e1);
            }
            ls += __shfl_xor_sync(0xffffffffu, ls, 1);
            ls += __shfl_xor_sync(0xffffffffu, ls, 2);
            l_[r] = l_[r] * fac + ls;
            m_[r] = mn;
            #pragma unroll
            for (int ni = 0; ni < 8; ni++) { acc[ni][r * 2] *= fac; acc[ni][r * 2 + 1] *= fac; }
        }

        // O += P V   (P fragments come straight from the S accumulator layout)
        #pragma unroll
        for (int kk = 0; kk < 4; kk++) {
            uint32_t a0 = *(uint32_t*)&ph[2 * kk][0];
            uint32_t a1 = *(uint32_t*)&ph[2 * kk][1];
            uint32_t a2 = *(uint32_t*)&ph[2 * kk + 1][0];
            uint32_t a3 = *(uint32_t*)&ph[2 * kk + 1][1];
            #pragma unroll
            for (int n2 = 0; n2 < 4; n2++) {
                uint32_t b0, b1, b2, b3;
                ldsm4t(b0, b1, b2, b3,
                       smem_u32(&Vs[st][kk * 16 + (lane & 15)][n2 * 16 + (lane >> 4) * 8]));
                mma16816(acc[n2 * 2],     a0, a1, a2, a3, b0, b1);
                mma16816(acc[n2 * 2 + 1], a0, a1, a2, a3, b2, b3);
            }
        }
    }

    float inv0 = 1.f / l_[0], inv1 = 1.f / l_[1];
    #pragma unroll
    for (int ni = 0; ni < 8; ni++) {
        int d = ni * 8 + (lane & 3) * 2;
        int t = t0 + w * 16 + (lane >> 2);
        *(__half2*)&Mg[(size_t)(b * Tt + t) * Cc + h * Dd + d] =
            __floats2half2_rn(acc[ni][0] * inv0, acc[ni][1] * inv0);
        *(__half2*)&Mg[(size_t)(b * Tt + t + 8) * Cc + h * Dd + d] =
            __floats2half2_rn(acc[ni][2] * inv1, acc[ni][3] * inv1);
    }
}

// ======================================================================
extern "C" void kernel_launch(void* const* d_in, const int* in_sizes, int n_in,
                              void* d_out, int out_size) {
    const float* x       = (const float*)d_in[0];
    const float* enc     = (const float*)d_in[1];
    const float* w_qkv   = (const float*)d_in[2];
    const float* w_proj  = (const float*)d_in[3];
    const float* b_proj  = (const float*)d_in[4];
    const float* cw_q    = (const float*)d_in[5];
    const float* cw_kv   = (const float*)d_in[6];
    const float* cw_proj = (const float*)d_in[7];
    const float* cb_proj = (const float*)d_in[8];
    const float* ff1_w1  = (const float*)d_in[9];
    const float* ff1_b1  = (const float*)d_in[10];
    const float* ff1_w2  = (const float*)d_in[11];
    const float* ff1_b2  = (const float*)d_in[12];
    const float* ff2_w1  = (const float*)d_in[13];
    const float* ff2_b1  = (const float*)d_in[14];
    const float* ff2_w2  = (const float*)d_in[15];
    const float* ff2_b2  = (const float*)d_in[16];
    const float* ln1_w = (const float*)d_in[17]; const float* ln1_b = (const float*)d_in[18];
    const float* ln2_w = (const float*)d_in[19]; const float* ln2_b = (const float*)d_in[20];
    const float* ln3_w = (const float*)d_in[21]; const float* ln3_b = (const float*)d_in[22];
    const float* ln4_w = (const float*)d_in[23]; const float* ln4_b = (const float*)d_in[24];

    float *px;
    __half *pln, *penc, *pwqkv, *pcwq, *pcwkv, *pwproj, *pcwproj;
    __half *pf11, *pf12, *pf21, *pf22;
    __half *py, *pm, *pff;
    cudaGetSymbolAddress((void**)&px,     g_x);
    cudaGetSymbolAddress((void**)&pln,    h_ln);
    cudaGetSymbolAddress((void**)&penc,   h_enc);
    cudaGetSymbolAddress((void**)&pwqkv,  h_wqkv);
    cudaGetSymbolAddress((void**)&pcwq,   h_cwq);
    cudaGetSymbolAddress((void**)&pcwkv,  h_cwkv);
    cudaGetSymbolAddress((void**)&pwproj, h_wproj);
    cudaGetSymbolAddress((void**)&pcwproj,h_cwproj);
    cudaGetSymbolAddress((void**)&pf11,   h_ff1w1);
    cudaGetSymbolAddress((void**)&pf12,   h_ff1w2);
    cudaGetSymbolAddress((void**)&pf21,   h_ff2w1);
    cudaGetSymbolAddress((void**)&pf22,   h_ff2w2);
    cudaGetSymbolAddress((void**)&py,     h_y);
    cudaGetSymbolAddress((void**)&pm,     h_m);
    cudaGetSymbolAddress((void**)&pff,    h_ff);

    cudaFuncSetAttribute(hgemm_kernel, cudaFuncAttributeMaxDynamicSharedMemorySize, HG_SMEM);
    cudaFuncSetAttribute(flash_kernel, cudaFuncAttributeMaxDynamicSharedMemorySize, FL_SMEM);

    auto cgrid = [](int n) { return (n + 255) / 256; };

    // ---- critical-path converts on the capture stream ----
    pack_w_kernel<<<cgrid(Hh*Cc*192/8), 256>>>(w_qkv, pwqkv, 192);
    cudaMemcpyAsync(px, x, (size_t)MM * Cc * sizeof(float), cudaMemcpyDeviceToDevice, 0);

    // ---- fork: all remaining converts on side stream, overlapped with attn 1 ----
    cudaEventRecord(g_ev1, 0);
    cudaStreamWaitEvent(g_s2, g_ev1, 0);
    pack_w_kernel<<<cgrid(Hh*Cc*64/8),  256, 0, g_s2>>>(cw_q,  pcwq,  64);
    pack_w_kernel<<<cgrid(Hh*Cc*128/8), 256, 0, g_s2>>>(cw_kv, pcwkv, 128);
    f2h_kernel<<<cgrid(Cc*Cc/4),  256, 0, g_s2>>>(w_proj,  pwproj,  Cc*Cc/4);
    f2h_kernel<<<cgrid(Cc*Cc/4),  256, 0, g_s2>>>(cw_proj, pcwproj, Cc*Cc/4);
    f2h_kernel<<<cgrid(Cc*FFF/4), 256, 0, g_s2>>>(ff1_w1, pf11, Cc*FFF/4);
    f2h_kernel<<<cgrid(FFF*Cc/4), 256, 0, g_s2>>>(ff1_w2, pf12, FFF*Cc/4);
    f2h_kernel<<<cgrid(Cc*FFF/4), 256, 0, g_s2>>>(ff2_w1, pf21, Cc*FFF/4);
    f2h_kernel<<<cgrid(FFF*Cc/4), 256, 0, g_s2>>>(ff2_w2, pf22, FFF*Cc/4);
    f2h_kernel<<<cgrid(MM*Cc/4),  256, 0, g_s2>>>(enc, penc, MM*Cc/4);
    cudaEventRecord(g_ev2, g_s2);

    // ---- 1) causal self-attention (overlaps the side-stream converts) ----
    ln_kernel<<<MM, 256>>>(px, ln1_w, ln1_b, pln);
    hgemm_kernel<<<dim3(24, 32), 256, HG_SMEM>>>(pln, pwqkv, nullptr, nullptr, nullptr, py, MM, 3072, Cc, 0);
    flash_kernel<<<dim3(8, NHEADS), 256, FL_SMEM>>>(py, py + 64, py + 128, pm, 3072, 192, 3072, 192, 1);

    // ---- join: all remaining weights ready ----
    cudaStreamWaitEvent(0, g_ev2, 0);

    hgemm_kernel<<<dim3(8, 32), 256, HG_SMEM>>>(pm, pwproj, b_proj, px, px, nullptr, MM, Cc, Cc, 0);

    // ---- 2) feed-forward 1 ----
    ln_kernel<<<MM, 256>>>(px, ln2_w, ln2_b, pln);
    hgemm_kernel<<<dim3(32, 32), 256, HG_SMEM>>>(pln, pf11, ff1_b1, nullptr, nullptr, pff, MM, FFF, Cc, 1);
    hgemm_kernel<<<dim3(8, 32), 256, HG_SMEM>>>(pff, pf12, ff1_b2, px, px, nullptr, MM, Cc, FFF, 0);

    // ---- 3) cross-attention ----
    ln_kernel<<<MM, 256>>>(px, ln3_w, ln3_b, pln);
    hgemm_kernel<<<dim3(8, 32), 256, HG_SMEM>>>(pln, pcwq, nullptr, nullptr, nullptr, py, MM, 1024, Cc, 0);
    __half* py2 = py + (size_t)MM * 1024;
    hgemm_kernel<<<dim3(16, 32), 256, HG_SMEM>>>(penc, pcwkv, nullptr, nullptr, nullptr, py2, MM, 2048, Cc, 0);
    flash_kernel<<<dim3(8, NHEADS), 256, FL_SMEM>>>(py, py2, py2 + 64, pm, 1024, 64, 2048, 128, 0);
    hgemm_kernel<<<dim3(8, 32), 256, HG_SMEM>>>(pm, pcwproj, cb_proj, px, px, nullptr, MM, Cc, Cc, 0);

    // ---- 4) feed-forward 2 (final output -> d_out) ----
    ln_kernel<<<MM, 256>>>(px, ln4_w, ln4_b, pln);
    hgemm_kernel<<<dim3(32, 32), 256, HG_SMEM>>>(pln, pf21, ff2_b1, nullptr, nullptr, pff, MM, FFF, Cc, 1);
    hgemm_kernel<<<dim3(8, 32), 256, HG_SMEM>>>(pff, pf22, ff2_b2, px, (float*)d_out, nullptr, MM, Cc, FFF, 0);
}

// round 7
// speedup vs baseline: 8.1178x; 1.0238x over previous
#include <cuda_runtime.h>
#include <cuda_fp16.h>
#include <cstdint>
#include <math.h>

#define Bz  4
#define Tt  1024
#define Cc  1024
#define Hh  16
#define Dd  64
#define FFF 4096
#define MM  (Bz*Tt)           // 4096
#define NHEADS (Bz*Hh)        // 64

// ---------------- scratch (device globals) ----------------
__device__ float  g_x   [MM*Cc];                 // fp32 residual stream
__device__ __half h_ln  [MM*Cc];
__device__ __half h_enc [MM*Cc];
__device__ __half h_wqkv[Cc*Hh*3*Dd];
__device__ __half h_cwq [Cc*Hh*Dd];
__device__ __half h_cwkv[Cc*Hh*2*Dd];
__device__ __half h_wproj[Cc*Cc];
__device__ __half h_cwproj[Cc*Cc];
__device__ __half h_ff1w1[Cc*FFF];
__device__ __half h_ff1w2[FFF*Cc];
__device__ __half h_ff2w1[Cc*FFF];
__device__ __half h_ff2w2[FFF*Cc];
__device__ __half h_y   [MM*Hh*3*Dd];            // qkv packed / cross-q
__device__ __half h_kv  [MM*Hh*2*Dd];            // cross-attn K|V packed (dedicated)
__device__ __half h_m   [MM*Cc];                 // merged attention out
__device__ __half h_ff  [MM*FFF];

// ---------------- side stream for overlap (created once, pre-main) ----------
static cudaStream_t g_s2;
static cudaEvent_t  g_ev1, g_ev2, g_ev3;
struct _StreamInit {
    _StreamInit() {
        cudaStreamCreateWithFlags(&g_s2, cudaStreamNonBlocking);
        cudaEventCreateWithFlags(&g_ev1, cudaEventDisableTiming);
        cudaEventCreateWithFlags(&g_ev2, cudaEventDisableTiming);
        cudaEventCreateWithFlags(&g_ev3, cudaEventDisableTiming);
    }
};
static _StreamInit _stream_init_once;

// ---------------- mma/ldmatrix/cp.async helpers ----------------
__device__ __forceinline__ uint32_t smem_u32(const void* p) {
    return (uint32_t)__cvta_generic_to_shared(p);
}
__device__ __forceinline__ void ldsm4(uint32_t& r0, uint32_t& r1, uint32_t& r2, uint32_t& r3, uint32_t a) {
    asm volatile("ldmatrix.sync.aligned.m8n8.x4.shared.b16 {%0,%1,%2,%3}, [%4];"
                 : "=r"(r0), "=r"(r1), "=r"(r2), "=r"(r3) : "r"(a));
}
__device__ __forceinline__ void ldsm4t(uint32_t& r0, uint32_t& r1, uint32_t& r2, uint32_t& r3, uint32_t a) {
    asm volatile("ldmatrix.sync.aligned.m8n8.x4.trans.shared.b16 {%0,%1,%2,%3}, [%4];"
                 : "=r"(r0), "=r"(r1), "=r"(r2), "=r"(r3) : "r"(a));
}
__device__ __forceinline__ void mma16816(float* c, uint32_t a0, uint32_t a1, uint32_t a2, uint32_t a3,
                                         uint32_t b0, uint32_t b1) {
    asm volatile("mma.sync.aligned.m16n8k16.row.col.f32.f16.f16.f32 "
                 "{%0,%1,%2,%3},{%4,%5,%6,%7},{%8,%9},{%0,%1,%2,%3};"
                 : "+f"(c[0]), "+f"(c[1]), "+f"(c[2]), "+f"(c[3])
                 : "r"(a0), "r"(a1), "r"(a2), "r"(a3), "r"(b0), "r"(b1));
}
__device__ __forceinline__ void cpa16(uint32_t dst, const void* src) {
    asm volatile("cp.async.cg.shared.global [%0], [%1], 16;" :: "r"(dst), "l"(src));
}
#define CP_COMMIT()  asm volatile("cp.async.commit_group;")
#define CP_WAIT(n)   asm volatile("cp.async.wait_group %0;" :: "n"(n) : "memory")

// ---------------- converts ----------------
__global__ void f2h_kernel(const float* __restrict__ src, __half* __restrict__ dst, int n4) {
    int i = blockIdx.x * blockDim.x + threadIdx.x;
    if (i >= n4) return;
    float4 v = ((const float4*)src)[i];
    __half2* o = (__half2*)dst + i * 2;
    o[0] = __floats2half2_rn(v.x, v.y);
    o[1] = __floats2half2_rn(v.z, v.w);
}
// W[H][C][J] -> Wt[C][H*J] fp16, 8 elements per thread
__global__ void pack_w_kernel(const float* __restrict__ W, __half* __restrict__ Wt, int J) {
    int i = blockIdx.x * blockDim.x + threadIdx.x;
    int J8 = J >> 3;
    int total8 = Hh * Cc * J8;
    if (i >= total8) return;
    int j8 = i % J8;
    int c = (i / J8) % Cc;
    int h = i / (J8 * Cc);
    const float4* src = (const float4*)(W + (size_t)(h * Cc + c) * J + j8 * 8);
    float4 v0 = src[0], v1 = src[1];
    __half2 o[4];
    o[0] = __floats2half2_rn(v0.x, v0.y); o[1] = __floats2half2_rn(v0.z, v0.w);
    o[2] = __floats2half2_rn(v1.x, v1.y); o[3] = __floats2half2_rn(v1.z, v1.w);
    *(uint4*)(Wt + (size_t)c * (Hh * J) + h * J + j8 * 8) = *(uint4*)o;
}

// ---------------- layernorm: warp-per-row, shfl-only reduction ----------------
__global__ void __launch_bounds__(256) ln_kernel(const float* __restrict__ X,
                                                 const float* __restrict__ w,
                                                 const float* __restrict__ b,
                                                 __half* __restrict__ Y) {
    int warp = threadIdx.x >> 5, lane = threadIdx.x & 31;
    int row = blockIdx.x * 8 + warp;
    const float4* x4 = (const float4*)(X + (size_t)row * Cc);
    float4 v[8];
    float s = 0.f, sq = 0.f;
    #pragma unroll
    for (int i = 0; i < 8; i++) {
        v[i] = x4[lane + i * 32];
        s  += v[i].x + v[i].y + v[i].z + v[i].w;
        sq += v[i].x*v[i].x + v[i].y*v[i].y + v[i].z*v[i].z + v[i].w*v[i].w;
    }
    #pragma unroll
    for (int o = 16; o > 0; o >>= 1) {
        s  += __shfl_xor_sync(0xffffffffu, s,  o);
        sq += __shfl_xor_sync(0xffffffffu, sq, o);
    }
    float mu   = s / Cc;
    float rstd = rsqrtf(sq / Cc - mu * mu + 1e-5f);
    const float4* w4 = (const float4*)w;
    const float4* b4 = (const float4*)b;
    uint2* y = (uint2*)(Y + (size_t)row * Cc);
    #pragma unroll
    for (int i = 0; i < 8; i++) {
        float4 wv = w4[lane + i * 32];
        float4 bv = b4[lane + i * 32];
        __half2 o0 = __floats2half2_rn((v[i].x - mu) * rstd * wv.x + bv.x,
                                       (v[i].y - mu) * rstd * wv.y + bv.y);
        __half2 o1 = __floats2half2_rn((v[i].z - mu) * rstd * wv.z + bv.z,
                                       (v[i].w - mu) * rstd * wv.w + bv.w);
        uint2 pk;
        pk.x = *(uint32_t*)&o0;
        pk.y = *(uint32_t*)&o1;
        y[lane + i * 32] = pk;
    }
}

// ---------------- fp16 tensor-core GEMM, 4-stage cp.async ring, 1 barrier/iter ----
// C = A[M,K]@B[K,N] (+bias)(+relu)(+res). outH!=null -> fp16 out, else fp32 outF.
#define HG_STAGES 4
#define HG_AS (128*40)
#define HG_BS (32*136)
#define HG_SMEM (HG_STAGES*(HG_AS+HG_BS)*2)   // 75776 bytes

__global__ void __launch_bounds__(256, 2) hgemm_kernel(const __half* __restrict__ A,
                                                       const __half* __restrict__ B,
                                                       const float* __restrict__ bias,
                                                       const float* __restrict__ res,
                                                       float* __restrict__ outF,
                                                       __half* __restrict__ outH,
                                                       int M, int N, int K, int relu) {
    extern __shared__ __half hsm[];
    __half (*As)[128][40] = (__half(*)[128][40])hsm;
    __half (*Bs)[32][136] = (__half(*)[32][136])(hsm + HG_STAGES * HG_AS);
    int tid = threadIdx.x, lane = tid & 31, warp = tid >> 5;
    int wm = warp >> 2, wn = warp & 3;
    int m0 = blockIdx.y * 128, n0 = blockIdx.x * 128;

    float acc[4][4][4] = {};

    auto load_stage = [&](int k0, int st) {
        #pragma unroll
        for (int j = 0; j < 2; j++) {
            int idx = tid + j * 256;
            int row = idx >> 2, c = (idx & 3) * 8;
            cpa16(smem_u32(&As[st][row][c]), A + (size_t)(m0 + row) * K + k0 + c);
        }
        #pragma unroll
        for (int j = 0; j < 2; j++) {
            int idx = tid + j * 256;
            int row = idx >> 4, c = (idx & 15) * 8;
            cpa16(smem_u32(&Bs[st][row][c]), B + (size_t)(k0 + row) * N + n0 + c);
        }
    };

    int nIter = K >> 5;
    load_stage(0, 0); CP_COMMIT();
    load_stage(32, 1); CP_COMMIT();

    for (int it = 0; it < nIter; it++) {
        if (it + 2 < nIter) load_stage((it + 2) << 5, (it + 2) & 3);
        CP_COMMIT();
        CP_WAIT(2);
        __syncthreads();
        int st = it & 3;
        #pragma unroll
        for (int kk = 0; kk < 32; kk += 16) {
            uint32_t a[4][4];
            #pragma unroll
            for (int mi = 0; mi < 4; mi++)
                ldsm4(a[mi][0], a[mi][1], a[mi][2], a[mi][3],
                      smem_u32(&As[st][wm * 64 + mi * 16 + (lane & 15)][kk + (lane >> 4) * 8]));
            #pragma unroll
            for (int n2 = 0; n2 < 2; n2++) {
                uint32_t b0, b1, b2, b3;
                ldsm4t(b0, b1, b2, b3,
                       smem_u32(&Bs[st][kk + (lane & 15)][wn * 32 + n2 * 16 + (lane >> 4) * 8]));
                #pragma unroll
                for (int mi = 0; mi < 4; mi++) {
                    mma16816(acc[mi][n2 * 2],     a[mi][0], a[mi][1], a[mi][2], a[mi][3], b0, b1);
                    mma16816(acc[mi][n2 * 2 + 1], a[mi][0], a[mi][1], a[mi][2], a[mi][3], b2, b3);
                }
            }
        }
    }

    #pragma unroll
    for (int mi = 0; mi < 4; mi++) {
        #pragma unroll
        for (int ni = 0; ni < 4; ni++) {
            int col = n0 + wn * 32 + ni * 8 + (lane & 3) * 2;
            #pragma unroll
            for (int r = 0; r < 2; r++) {
                int row = m0 + wm * 64 + mi * 16 + (lane >> 2) + r * 8;
                float v0 = acc[mi][ni][r * 2], v1 = acc[mi][ni][r * 2 + 1];
                if (bias) { v0 += bias[col]; v1 += bias[col + 1]; }
                if (relu) { v0 = fmaxf(v0, 0.f); v1 = fmaxf(v1, 0.f); }
                size_t idx = (size_t)row * N + col;
                if (res) { v0 += res[idx]; v1 += res[idx + 1]; }
                if (outH) {
                    *(__half2*)&outH[idx] = __floats2half2_rn(v0, v1);
                } else {
                    *(float2*)&outF[idx] = make_float2(v0, v1);
                }
            }
        }
    }
}

// ---------------- fused flash attention, 4-stage cp.async K/V ring ----------------
#define FL_QS (128*72)
#define FL_KS (64*72)
#define FL_SMEM ((FL_QS + 8*FL_KS)*2)    // 92160 bytes

__global__ void __launch_bounds__(256, 2) flash_kernel(const __half* __restrict__ Q,
                                                       const __half* __restrict__ Kp,
                                                       const __half* __restrict__ Vp,
                                                       __half* __restrict__ Mg,
                                                       int strideQ, int pitchQ,
                                                       int strideKV, int pitchKV, int causal) {
    extern __shared__ __half fsm[];
    __half (*Qs)[72] = (__half(*)[72])fsm;
    __half (*Ks)[64][72] = (__half(*)[64][72])(fsm + FL_QS);
    __half (*Vs)[64][72] = (__half(*)[64][72])(fsm + FL_QS + 4 * FL_KS);
    int tid = threadIdx.x, lane = tid & 31, w = tid >> 5;
    int bh = blockIdx.y, b = bh >> 4, h = bh & 15;
    int t0 = blockIdx.x * 128;
    const __half* Qb = Q  + (size_t)b * Tt * strideQ  + h * pitchQ;
    const __half* Kb = Kp + (size_t)b * Tt * strideKV + h * pitchKV;
    const __half* Vb = Vp + (size_t)b * Tt * strideKV + h * pitchKV;

    auto load_kv = [&](int s0, int st) {
        #pragma unroll
        for (int j = 0; j < 2; j++) {
            int idx = tid + j * 256;
            int row = idx >> 3, col = (idx & 7) * 8;
            cpa16(smem_u32(&Ks[st][row][col]), Kb + (size_t)(s0 + row) * strideKV + col);
            cpa16(smem_u32(&Vs[st][row][col]), Vb + (size_t)(s0 + row) * strideKV + col);
        }
    };

    int sEnd = causal ? (t0 + 128) : Tt;
    int nT = sEnd >> 6;
    load_kv(0, 0); CP_COMMIT();
    if (nT > 1) load_kv(64, 1);
    CP_COMMIT();

    const __half2 sc = __float2half2_rn(0.125f);
    #pragma unroll
    for (int j = 0; j < 4; j++) {
        int idx = tid + j * 256;
        int row = idx >> 3, col = (idx & 7) * 8;
        uint4 v = *(const uint4*)(Qb + (size_t)(t0 + row) * strideQ + col);
        __half2* h2 = (__half2*)&v;
        #pragma unroll
        for (int q = 0; q < 4; q++) h2[q] = __hmul2(h2[q], sc);
        *(uint4*)&Qs[row][col] = v;
    }
    __syncthreads();

    uint32_t qf[4][4];
    #pragma unroll
    for (int kk = 0; kk < 4; kk++)
        ldsm4(qf[kk][0], qf[kk][1], qf[kk][2], qf[kk][3],
              smem_u32(&Qs[w * 16 + (lane & 15)][kk * 16 + (lane >> 4) * 8]));

    float m_[2] = {-1e30f, -1e30f}, l_[2] = {0.f, 0.f};
    float acc[8][4] = {};

    for (int i = 0; i < nT; i++) {
        if (i + 2 < nT) load_kv((i + 2) << 6, (i + 2) & 3);
        CP_COMMIT();
        CP_WAIT(2);
        __syncthreads();
        int st = i & 3;
        int s0 = i << 6;

        float sacc[8][4] = {};
        #pragma unroll
        for (int kk = 0; kk < 4; kk++) {
            #pragma unroll
            for (int sg = 0; sg < 4; sg++) {
                uint32_t b0, b1, b2, b3;
                ldsm4(b0, b1, b2, b3,
                      smem_u32(&Ks[st][sg * 16 + (lane & 7) + ((lane >> 4) << 3)][kk * 16 + ((lane >> 3) & 1) * 8]));
                mma16816(sacc[sg * 2],     qf[kk][0], qf[kk][1], qf[kk][2], qf[kk][3], b0, b1);
                mma16816(sacc[sg * 2 + 1], qf[kk][0], qf[kk][1], qf[kk][2], qf[kk][3], b2, b3);
            }
        }

        if (causal && s0 + 63 > t0 + w * 16) {
            int tr0 = t0 + w * 16 + (lane >> 2);
            int tr1 = tr0 + 8;
            #pragma unroll
            for (int ni = 0; ni < 8; ni++) {
                int s = s0 + ni * 8 + (lane & 3) * 2;
                if (s > tr0)     sacc[ni][0] = -1e30f;
                if (s + 1 > tr0) sacc[ni][1] = -1e30f;
                if (s > tr1)     sacc[ni][2] = -1e30f;
                if (s + 1 > tr1) sacc[ni][3] = -1e30f;
            }
        }

        __half2 ph[8][2];
        #pragma unroll
        for (int r = 0; r < 2; r++) {
            float rm = -1e30f;
            #pragma unroll
            for (int ni = 0; ni < 8; ni++)
                rm = fmaxf(rm, fmaxf(sacc[ni][r * 2], sacc[ni][r * 2 + 1]));
            rm = fmaxf(rm, __shfl_xor_sync(0xffffffffu, rm, 1));
            rm = fmaxf(rm, __shfl_xor_sync(0xffffffffu, rm, 2));
            float mn  = fmaxf(m_[r], rm);
            float fac = __expf(m_[r] - mn);
            float ls = 0.f;
            #pragma unroll
            for (int ni = 0; ni < 8; ni++) {
                float e0 = __expf(sacc[ni][r * 2]     - mn);
                float e1 = __expf(sacc[ni][r * 2 + 1] - mn);
                ls += e0 + e1;
                ph[ni][r] = __floats2half2_rn(e0, e1);
            }
            ls += __shfl_xor_sync(0xffffffffu, ls, 1);
            ls += __shfl_xor_sync(0xffffffffu, ls, 2);
            l_[r] = l_[r] * fac + ls;
            m_[r] = mn;
            #pragma unroll
            for (int ni = 0; ni < 8; ni++) { acc[ni][r * 2] *= fac; acc[ni][r * 2 + 1] *= fac; }
        }

        #pragma unroll
        for (int kk = 0; kk < 4; kk++) {
            uint32_t a0 = *(uint32_t*)&ph[2 * kk][0];
            uint32_t a1 = *(uint32_t*)&ph[2 * kk][1];
            uint32_t a2 = *(uint32_t*)&ph[2 * kk + 1][0];
            uint32_t a3 = *(uint32_t*)&ph[2 * kk + 1][1];
            #pragma unroll
            for (int n2 = 0; n2 < 4; n2++) {
                uint32_t b0, b1, b2, b3;
                ldsm4t(b0, b1, b2, b3,
                       smem_u32(&Vs[st][kk * 16 + (lane & 15)][n2 * 16 + (lane >> 4) * 8]));
                mma16816(acc[n2 * 2],     a0, a1, a2, a3, b0, b1);
                mma16816(acc[n2 * 2 + 1], a0, a1, a2, a3, b2, b3);
            }
        }
    }

    float inv0 = 1.f / l_[0], inv1 = 1.f / l_[1];
    #pragma unroll
    for (int ni = 0; ni < 8; ni++) {
        int d = ni * 8 + (lane & 3) * 2;
        int t = t0 + w * 16 + (lane >> 2);
        *(__half2*)&Mg[(size_t)(b * Tt + t) * Cc + h * Dd + d] =
            __floats2half2_rn(acc[ni][0] * inv0, acc[ni][1] * inv0);
        *(__half2*)&Mg[(size_t)(b * Tt + t + 8) * Cc + h * Dd + d] =
            __floats2half2_rn(acc[ni][2] * inv1, acc[ni][3] * inv1);
    }
}

// ======================================================================
extern "C" void kernel_launch(void* const* d_in, const int* in_sizes, int n_in,
                              void* d_out, int out_size) {
    const float* x       = (const float*)d_in[0];
    const float* enc     = (const float*)d_in[1];
    const float* w_qkv   = (const float*)d_in[2];
    const float* w_proj  = (const float*)d_in[3];
    const float* b_proj  = (const float*)d_in[4];
    const float* cw_q    = (const float*)d_in[5];
    const float* cw_kv   = (const float*)d_in[6];
    const float* cw_proj = (const float*)d_in[7];
    const float* cb_proj = (const float*)d_in[8];
    const float* ff1_w1  = (const float*)d_in[9];
    const float* ff1_b1  = (const float*)d_in[10];
    const float* ff1_w2  = (const float*)d_in[11];
    const float* ff1_b2  = (const float*)d_in[12];
    const float* ff2_w1  = (const float*)d_in[13];
    const float* ff2_b1  = (const float*)d_in[14];
    const float* ff2_w2  = (const float*)d_in[15];
    const float* ff2_b2  = (const float*)d_in[16];
    const float* ln1_w = (const float*)d_in[17]; const float* ln1_b = (const float*)d_in[18];
    const float* ln2_w = (const float*)d_in[19]; const float* ln2_b = (const float*)d_in[20];
    const float* ln3_w = (const float*)d_in[21]; const float* ln3_b = (const float*)d_in[22];
    const float* ln4_w = (const float*)d_in[23]; const float* ln4_b = (const float*)d_in[24];

    float *px;
    __half *pln, *penc, *pwqkv, *pcwq, *pcwkv, *pwproj, *pcwproj;
    __half *pf11, *pf12, *pf21, *pf22;
    __half *py, *pkv, *pm, *pff;
    cudaGetSymbolAddress((void**)&px,     g_x);
    cudaGetSymbolAddress((void**)&pln,    h_ln);
    cudaGetSymbolAddress((void**)&penc,   h_enc);
    cudaGetSymbolAddress((void**)&pwqkv,  h_wqkv);
    cudaGetSymbolAddress((void**)&pcwq,   h_cwq);
    cudaGetSymbolAddress((void**)&pcwkv,  h_cwkv);
    cudaGetSymbolAddress((void**)&pwproj, h_wproj);
    cudaGetSymbolAddress((void**)&pcwproj,h_cwproj);
    cudaGetSymbolAddress((void**)&pf11,   h_ff1w1);
    cudaGetSymbolAddress((void**)&pf12,   h_ff1w2);
    cudaGetSymbolAddress((void**)&pf21,   h_ff2w1);
    cudaGetSymbolAddress((void**)&pf22,   h_ff2w2);
    cudaGetSymbolAddress((void**)&py,     h_y);
    cudaGetSymbolAddress((void**)&pkv,    h_kv);
    cudaGetSymbolAddress((void**)&pm,     h_m);
    cudaGetSymbolAddress((void**)&pff,    h_ff);

    cudaFuncSetAttribute(hgemm_kernel, cudaFuncAttributeMaxDynamicSharedMemorySize, HG_SMEM);
    cudaFuncSetAttribute(flash_kernel, cudaFuncAttributeMaxDynamicSharedMemorySize, FL_SMEM);

    auto cgrid = [](int n) { return (n + 255) / 256; };

    // ---- critical-path converts on the capture stream ----
    pack_w_kernel<<<cgrid(Hh*Cc*192/8), 256>>>(w_qkv, pwqkv, 192);
    cudaMemcpyAsync(px, x, (size_t)MM * Cc * sizeof(float), cudaMemcpyDeviceToDevice, 0);

    // ---- fork: converts + cross-KV GEMM on side stream, overlapped with attn 1/FF1 ----
    cudaEventRecord(g_ev1, 0);
    cudaStreamWaitEvent(g_s2, g_ev1, 0);
    pack_w_kernel<<<cgrid(Hh*Cc*64/8),  256, 0, g_s2>>>(cw_q,  pcwq,  64);
    pack_w_kernel<<<cgrid(Hh*Cc*128/8), 256, 0, g_s2>>>(cw_kv, pcwkv, 128);
    f2h_kernel<<<cgrid(Cc*Cc/4),  256, 0, g_s2>>>(w_proj,  pwproj,  Cc*Cc/4);
    f2h_kernel<<<cgrid(Cc*Cc/4),  256, 0, g_s2>>>(cw_proj, pcwproj, Cc*Cc/4);
    f2h_kernel<<<cgrid(Cc*FFF/4), 256, 0, g_s2>>>(ff1_w1, pf11, Cc*FFF/4);
    f2h_kernel<<<cgrid(FFF*Cc/4), 256, 0, g_s2>>>(ff1_w2, pf12, FFF*Cc/4);
    f2h_kernel<<<cgrid(Cc*FFF/4), 256, 0, g_s2>>>(ff2_w1, pf21, Cc*FFF/4);
    f2h_kernel<<<cgrid(FFF*Cc/4), 256, 0, g_s2>>>(ff2_w2, pf22, FFF*Cc/4);
    f2h_kernel<<<cgrid(MM*Cc/4),  256, 0, g_s2>>>(enc, penc, MM*Cc/4);
    cudaEventRecord(g_ev2, g_s2);            // weights ready
    // cross-attn KV GEMM off the critical path (depends only on enc + cw_kv)
    hgemm_kernel<<<dim3(16, 32), 256, HG_SMEM, g_s2>>>(penc, pcwkv, nullptr, nullptr, nullptr, pkv, MM, 2048, Cc, 0);
    cudaEventRecord(g_ev3, g_s2);            // cross K/V ready

    // ---- 1) causal self-attention (overlaps the side-stream work) ----
    ln_kernel<<<MM/8, 256>>>(px, ln1_w, ln1_b, pln);
    hgemm_kernel<<<dim3(24, 32), 256, HG_SMEM>>>(pln, pwqkv, nullptr, nullptr, nullptr, py, MM, 3072, Cc, 0);
    flash_kernel<<<dim3(8, NHEADS), 256, FL_SMEM>>>(py, py + 64, py + 128, pm, 3072, 192, 3072, 192, 1);

    cudaStreamWaitEvent(0, g_ev2, 0);        // weights ready
    hgemm_kernel<<<dim3(8, 32), 256, HG_SMEM>>>(pm, pwproj, b_proj, px, px, nullptr, MM, Cc, Cc, 0);

    // ---- 2) feed-forward 1 ----
    ln_kernel<<<MM/8, 256>>>(px, ln2_w, ln2_b, pln);
    hgemm_kernel<<<dim3(32, 32), 256, HG_SMEM>>>(pln, pf11, ff1_b1, nullptr, nullptr, pff, MM, FFF, Cc, 1);
    hgemm_kernel<<<dim3(8, 32), 256, HG_SMEM>>>(pff, pf12, ff1_b2, px, px, nullptr, MM, Cc, FFF, 0);

    // ---- 3) cross-attention ----
    ln_kernel<<<MM/8, 256>>>(px, ln3_w, ln3_b, pln);
    hgemm_kernel<<<dim3(8, 32), 256, HG_SMEM>>>(pln, pcwq, nullptr, nullptr, nullptr, py, MM, 1024, Cc, 0);
    cudaStreamWaitEvent(0, g_ev3, 0);        // cross K/V ready (long done by now)
    flash_kernel<<<dim3(8, NHEADS), 256, FL_SMEM>>>(py, pkv, pkv + 64, pm, 1024, 64, 2048, 128, 0);
    hgemm_kernel<<<dim3(8, 32), 256, HG_SMEM>>>(pm, pcwproj, cb_proj, px, px, nullptr, MM, Cc, Cc, 0);

    // ---- 4) feed-forward 2 (final output -> d_out) ----
    ln_kernel<<<MM/8, 256>>>(px, ln4_w, ln4_b, pln);
    hgemm_kernel<<<dim3(32, 32), 256, HG_SMEM>>>(pln, pf21, ff2_b1, nullptr, nullptr, pff, MM, FFF, Cc, 1);
    hgemm_kernel<<<dim3(8, 32), 256, HG_SMEM>>>(pff, pf22, ff2_b2, px, (float*)d_out, nullptr, MM, Cc, FFF, 0);
}

// round 9
// speedup vs baseline: 8.1376x; 1.0024x over previous
#include <cuda_runtime.h>
#include <cuda_fp16.h>
#include <cstdint>
#include <math.h>

#define Bz  4
#define Tt  1024
#define Cc  1024
#define Hh  16
#define Dd  64
#define FFF 4096
#define MM  (Bz*Tt)           // 4096
#define NHEADS (Bz*Hh)        // 64

// ---------------- scratch (device globals) ----------------
__device__ float  g_x   [MM*Cc];                 // fp32 residual stream
__device__ __half h_ln  [MM*Cc];
__device__ __half h_enc [MM*Cc];
__device__ __half h_wqkv[Cc*Hh*3*Dd];
__device__ __half h_cwq [Cc*Hh*Dd];
__device__ __half h_cwkv[Cc*Hh*2*Dd];
__device__ __half h_wproj[Cc*Cc];
__device__ __half h_cwproj[Cc*Cc];
__device__ __half h_ff1w1[Cc*FFF];
__device__ __half h_ff1w2[FFF*Cc];
__device__ __half h_ff2w1[Cc*FFF];
__device__ __half h_ff2w2[FFF*Cc];
__device__ __half h_y   [MM*Hh*3*Dd];            // self-attn qkv packed
__device__ __half h_cq  [MM*Cc];                 // cross-attn Q (dedicated; no aliasing across streams)
__device__ __half h_kv  [MM*Hh*2*Dd];            // cross-attn K|V packed
__device__ __half h_m   [MM*Cc];                 // merged attention out
__device__ __half h_ff  [MM*FFF];

// ---------------- streams/events (created once, pre-main) ----------------
static cudaStream_t g_s2, g_sb[3];               // converts stream + batch streams 1..3
static cudaEvent_t  g_ev1, g_ev2, g_ev3, g_evb[3];
struct _StreamInit {
    _StreamInit() {
        cudaStreamCreateWithFlags(&g_s2, cudaStreamNonBlocking);
        for (int i = 0; i < 3; i++) cudaStreamCreateWithFlags(&g_sb[i], cudaStreamNonBlocking);
        cudaEventCreateWithFlags(&g_ev1, cudaEventDisableTiming);
        cudaEventCreateWithFlags(&g_ev2, cudaEventDisableTiming);
        cudaEventCreateWithFlags(&g_ev3, cudaEventDisableTiming);
        for (int i = 0; i < 3; i++) cudaEventCreateWithFlags(&g_evb[i], cudaEventDisableTiming);
    }
};
static _StreamInit _stream_init_once;

// ---------------- mma/ldmatrix/cp.async helpers ----------------
__device__ __forceinline__ uint32_t smem_u32(const void* p) {
    return (uint32_t)__cvta_generic_to_shared(p);
}
__device__ __forceinline__ void ldsm4(uint32_t& r0, uint32_t& r1, uint32_t& r2, uint32_t& r3, uint32_t a) {
    asm volatile("ldmatrix.sync.aligned.m8n8.x4.shared.b16 {%0,%1,%2,%3}, [%4];"
                 : "=r"(r0), "=r"(r1), "=r"(r2), "=r"(r3) : "r"(a));
}
__device__ __forceinline__ void ldsm4t(uint32_t& r0, uint32_t& r1, uint32_t& r2, uint32_t& r3, uint32_t a) {
    asm volatile("ldmatrix.sync.aligned.m8n8.x4.trans.shared.b16 {%0,%1,%2,%3}, [%4];"
                 : "=r"(r0), "=r"(r1), "=r"(r2), "=r"(r3) : "r"(a));
}
__device__ __forceinline__ void mma16816(float* c, uint32_t a0, uint32_t a1, uint32_t a2, uint32_t a3,
                                         uint32_t b0, uint32_t b1) {
    asm volatile("mma.sync.aligned.m16n8k16.row.col.f32.f16.f16.f32 "
                 "{%0,%1,%2,%3},{%4,%5,%6,%7},{%8,%9},{%0,%1,%2,%3};"
                 : "+f"(c[0]), "+f"(c[1]), "+f"(c[2]), "+f"(c[3])
                 : "r"(a0), "r"(a1), "r"(a2), "r"(a3), "r"(b0), "r"(b1));
}
__device__ __forceinline__ void cpa16(uint32_t dst, const void* src) {
    asm volatile("cp.async.cg.shared.global [%0], [%1], 16;" :: "r"(dst), "l"(src));
}
#define CP_COMMIT()  asm volatile("cp.async.commit_group;")
#define CP_WAIT(n)   asm volatile("cp.async.wait_group %0;" :: "n"(n) : "memory")

// ---------------- converts ----------------
__global__ void f2h_kernel(const float* __restrict__ src, __half* __restrict__ dst, int n4) {
    int i = blockIdx.x * blockDim.x + threadIdx.x;
    if (i >= n4) return;
    float4 v = ((const float4*)src)[i];
    __half2* o = (__half2*)dst + i * 2;
    o[0] = __floats2half2_rn(v.x, v.y);
    o[1] = __floats2half2_rn(v.z, v.w);
}
// W[H][C][J] -> Wt[C][H*J] fp16, 8 elements per thread
__global__ void pack_w_kernel(const float* __restrict__ W, __half* __restrict__ Wt, int J) {
    int i = blockIdx.x * blockDim.x + threadIdx.x;
    int J8 = J >> 3;
    int total8 = Hh * Cc * J8;
    if (i >= total8) return;
    int j8 = i % J8;
    int c = (i / J8) % Cc;
    int h = i / (J8 * Cc);
    const float4* src = (const float4*)(W + (size_t)(h * Cc + c) * J + j8 * 8);
    float4 v0 = src[0], v1 = src[1];
    __half2 o[4];
    o[0] = __floats2half2_rn(v0.x, v0.y); o[1] = __floats2half2_rn(v0.z, v0.w);
    o[2] = __floats2half2_rn(v1.x, v1.y); o[3] = __floats2half2_rn(v1.z, v1.w);
    *(uint4*)(Wt + (size_t)c * (Hh * J) + h * J + j8 * 8) = *(uint4*)o;
}

// ---------------- layernorm: warp-per-row, shfl-only reduction ----------------
__global__ void __launch_bounds__(256) ln_kernel(const float* __restrict__ X,
                                                 const float* __restrict__ w,
                                                 const float* __restrict__ b,
                                                 __half* __restrict__ Y) {
    int warp = threadIdx.x >> 5, lane = threadIdx.x & 31;
    int row = blockIdx.x * 8 + warp;
    const float4* x4 = (const float4*)(X + (size_t)row * Cc);
    float4 v[8];
    float s = 0.f, sq = 0.f;
    #pragma unroll
    for (int i = 0; i < 8; i++) {
        v[i] = x4[lane + i * 32];
        s  += v[i].x + v[i].y + v[i].z + v[i].w;
        sq += v[i].x*v[i].x + v[i].y*v[i].y + v[i].z*v[i].z + v[i].w*v[i].w;
    }
    #pragma unroll
    for (int o = 16; o > 0; o >>= 1) {
        s  += __shfl_xor_sync(0xffffffffu, s,  o);
        sq += __shfl_xor_sync(0xffffffffu, sq, o);
    }
    float mu   = s / Cc;
    float rstd = rsqrtf(sq / Cc - mu * mu + 1e-5f);
    const float4* w4 = (const float4*)w;
    const float4* b4 = (const float4*)b;
    uint2* y = (uint2*)(Y + (size_t)row * Cc);
    #pragma unroll
    for (int i = 0; i < 8; i++) {
        float4 wv = w4[lane + i * 32];
        float4 bv = b4[lane + i * 32];
        __half2 o0 = __floats2half2_rn((v[i].x - mu) * rstd * wv.x + bv.x,
                                       (v[i].y - mu) * rstd * wv.y + bv.y);
        __half2 o1 = __floats2half2_rn((v[i].z - mu) * rstd * wv.z + bv.z,
                                       (v[i].w - mu) * rstd * wv.w + bv.w);
        uint2 pk;
        pk.x = *(uint32_t*)&o0;
        pk.y = *(uint32_t*)&o1;
        y[lane + i * 32] = pk;
    }
}

// ---------------- fp16 tensor-core GEMM, 4-stage cp.async ring, 1 barrier/iter ----
// C = A[M,K]@B[K,N] (+bias)(+relu)(+res). outH!=null -> fp16 out, else fp32 outF.
#define HG_STAGES 4
#define HG_AS (128*40)
#define HG_BS (32*136)
#define HG_SMEM (HG_STAGES*(HG_AS+HG_BS)*2)   // 75776 bytes

__global__ void __launch_bounds__(256, 2) hgemm_kernel(const __half* __restrict__ A,
                                                       const __half* __restrict__ B,
                                                       const float* __restrict__ bias,
                                                       const float* __restrict__ res,
                                                       float* __restrict__ outF,
                                                       __half* __restrict__ outH,
                                                       int M, int N, int K, int relu) {
    extern __shared__ __half hsm[];
    __half (*As)[128][40] = (__half(*)[128][40])hsm;
    __half (*Bs)[32][136] = (__half(*)[32][136])(hsm + HG_STAGES * HG_AS);
    int tid = threadIdx.x, lane = tid & 31, warp = tid >> 5;
    int wm = warp >> 2, wn = warp & 3;
    int m0 = blockIdx.y * 128, n0 = blockIdx.x * 128;

    float acc[4][4][4] = {};

    auto load_stage = [&](int k0, int st) {
        #pragma unroll
        for (int j = 0; j < 2; j++) {
            int idx = tid + j * 256;
            int row = idx >> 2, c = (idx & 3) * 8;
            cpa16(smem_u32(&As[st][row][c]), A + (size_t)(m0 + row) * K + k0 + c);
        }
        #pragma unroll
        for (int j = 0; j < 2; j++) {
            int idx = tid + j * 256;
            int row = idx >> 4, c = (idx & 15) * 8;
            cpa16(smem_u32(&Bs[st][row][c]), B + (size_t)(k0 + row) * N + n0 + c);
        }
    };

    int nIter = K >> 5;
    load_stage(0, 0); CP_COMMIT();
    load_stage(32, 1); CP_COMMIT();

    for (int it = 0; it < nIter; it++) {
        if (it + 2 < nIter) load_stage((it + 2) << 5, (it + 2) & 3);
        CP_COMMIT();
        CP_WAIT(2);
        __syncthreads();
        int st = it & 3;
        #pragma unroll
        for (int kk = 0; kk < 32; kk += 16) {
            uint32_t a[4][4];
            #pragma unroll
            for (int mi = 0; mi < 4; mi++)
                ldsm4(a[mi][0], a[mi][1], a[mi][2], a[mi][3],
                      smem_u32(&As[st][wm * 64 + mi * 16 + (lane & 15)][kk + (lane >> 4) * 8]));
            #pragma unroll
            for (int n2 = 0; n2 < 2; n2++) {
                uint32_t b0, b1, b2, b3;
                ldsm4t(b0, b1, b2, b3,
                       smem_u32(&Bs[st][kk + (lane & 15)][wn * 32 + n2 * 16 + (lane >> 4) * 8]));
                #pragma unroll
                for (int mi = 0; mi < 4; mi++) {
                    mma16816(acc[mi][n2 * 2],     a[mi][0], a[mi][1], a[mi][2], a[mi][3], b0, b1);
                    mma16816(acc[mi][n2 * 2 + 1], a[mi][0], a[mi][1], a[mi][2], a[mi][3], b2, b3);
                }
            }
        }
    }

    #pragma unroll
    for (int mi = 0; mi < 4; mi++) {
        #pragma unroll
        for (int ni = 0; ni < 4; ni++) {
            int col = n0 + wn * 32 + ni * 8 + (lane & 3) * 2;
            #pragma unroll
            for (int r = 0; r < 2; r++) {
                int row = m0 + wm * 64 + mi * 16 + (lane >> 2) + r * 8;
                float v0 = acc[mi][ni][r * 2], v1 = acc[mi][ni][r * 2 + 1];
                if (bias) { v0 += bias[col]; v1 += bias[col + 1]; }
                if (relu) { v0 = fmaxf(v0, 0.f); v1 = fmaxf(v1, 0.f); }
                size_t idx = (size_t)row * N + col;
                if (res) { v0 += res[idx]; v1 += res[idx + 1]; }
                if (outH) {
                    *(__half2*)&outH[idx] = __floats2half2_rn(v0, v1);
                } else {
                    *(float2*)&outF[idx] = make_float2(v0, v1);
                }
            }
        }
    }
}

// ---------------- fused flash attention, 4-stage cp.async K/V ring ----------------
// Per-batch: pointers pre-offset to this batch; grid.y = heads (16).
// Heavy-first ordering: largest t-tile launched first (causal load balance).
#define FL_QS (128*72)
#define FL_KS (64*72)
#define FL_SMEM ((FL_QS + 8*FL_KS)*2)    // 92160 bytes

__global__ void __launch_bounds__(256, 2) flash_kernel(const __half* __restrict__ Q,
                                                       const __half* __restrict__ Kp,
                                                       const __half* __restrict__ Vp,
                                                       __half* __restrict__ Mg,
                                                       int strideQ, int pitchQ,
                                                       int strideKV, int pitchKV, int causal) {
    extern __shared__ __half fsm[];
    __half (*Qs)[72] = (__half(*)[72])fsm;
    __half (*Ks)[64][72] = (__half(*)[64][72])(fsm + FL_QS);
    __half (*Vs)[64][72] = (__half(*)[64][72])(fsm + FL_QS + 4 * FL_KS);
    int tid = threadIdx.x, lane = tid & 31, w = tid >> 5;
    int h = blockIdx.y;
    int t0 = (gridDim.x - 1 - blockIdx.x) * 128;    // heavy tiles first
    const __half* Qb = Q  + h * pitchQ;
    const __half* Kb = Kp + h * pitchKV;
    const __half* Vb = Vp + h * pitchKV;

    auto load_kv = [&](int s0, int st) {
        #pragma unroll
        for (int j = 0; j < 2; j++) {
            int idx = tid + j * 256;
            int row = idx >> 3, col = (idx & 7) * 8;
            cpa16(smem_u32(&Ks[st][row][col]), Kb + (size_t)(s0 + row) * strideKV + col);
            cpa16(smem_u32(&Vs[st][row][col]), Vb + (size_t)(s0 + row) * strideKV + col);
        }
    };

    int sEnd = causal ? (t0 + 128) : Tt;
    int nT = sEnd >> 6;
    load_kv(0, 0); CP_COMMIT();
    if (nT > 1) load_kv(64, 1);
    CP_COMMIT();

    const __half2 sc = __float2half2_rn(0.125f);
    #pragma unroll
    for (int j = 0; j < 4; j++) {
        int idx = tid + j * 256;
        int row = idx >> 3, col = (idx & 7) * 8;
        uint4 v = *(const uint4*)(Qb + (size_t)(t0 + row) * strideQ + col);
        __half2* h2 = (__half2*)&v;
        #pragma unroll
        for (int q = 0; q < 4; q++) h2[q] = __hmul2(h2[q], sc);
        *(uint4*)&Qs[row][col] = v;
    }
    __syncthreads();

    uint32_t qf[4][4];
    #pragma unroll
    for (int kk = 0; kk < 4; kk++)
        ldsm4(qf[kk][0], qf[kk][1], qf[kk][2], qf[kk][3],
              smem_u32(&Qs[w * 16 + (lane & 15)][kk * 16 + (lane >> 4) * 8]));

    float m_[2] = {-1e30f, -1e30f}, l_[2] = {0.f, 0.f};
    float acc[8][4] = {};

    for (int i = 0; i < nT; i++) {
        if (i + 2 < nT) load_kv((i + 2) << 6, (i + 2) & 3);
        CP_COMMIT();
        CP_WAIT(2);
        __syncthreads();
        int st = i & 3;
        int s0 = i << 6;

        float sacc[8][4] = {};
        #pragma unroll
        for (int kk = 0; kk < 4; kk++) {
            #pragma unroll
            for (int sg = 0; sg < 4; sg++) {
                uint32_t b0, b1, b2, b3;
                ldsm4(b0, b1, b2, b3,
                      smem_u32(&Ks[st][sg * 16 + (lane & 7) + ((lane >> 4) << 3)][kk * 16 + ((lane >> 3) & 1) * 8]));
                mma16816(sacc[sg * 2],     qf[kk][0], qf[kk][1], qf[kk][2], qf[kk][3], b0, b1);
                mma16816(sacc[sg * 2 + 1], qf[kk][0], qf[kk][1], qf[kk][2], qf[kk][3], b2, b3);
            }
        }

        if (causal && s0 + 63 > t0 + w * 16) {
            int tr0 = t0 + w * 16 + (lane >> 2);
            int tr1 = tr0 + 8;
            #pragma unroll
            for (int ni = 0; ni < 8; ni++) {
                int s = s0 + ni * 8 + (lane & 3) * 2;
                if (s > tr0)     sacc[ni][0] = -1e30f;
                if (s + 1 > tr0) sacc[ni][1] = -1e30f;
                if (s > tr1)     sacc[ni][2] = -1e30f;
                if (s + 1 > tr1) sacc[ni][3] = -1e30f;
            }
        }

        __half2 ph[8][2];
        #pragma unroll
        for (int r = 0; r < 2; r++) {
            float rm = -1e30f;
            #pragma unroll
            for (int ni = 0; ni < 8; ni++)
                rm = fmaxf(rm, fmaxf(sacc[ni][r * 2], sacc[ni][r * 2 + 1]));
            rm = fmaxf(rm, __shfl_xor_sync(0xffffffffu, rm, 1));
            rm = fmaxf(rm, __shfl_xor_sync(0xffffffffu, rm, 2));
            float mn  = fmaxf(m_[r], rm);
            float fac = __expf(m_[r] - mn);
            float ls = 0.f;
            #pragma unroll
            for (int ni = 0; ni < 8; ni++) {
                float e0 = __expf(sacc[ni][r * 2]     - mn);
                float e1 = __expf(sacc[ni][r * 2 + 1] - mn);
                ls += e0 + e1;
                ph[ni][r] = __floats2half2_rn(e0, e1);
            }
            ls += __shfl_xor_sync(0xffffffffu, ls, 1);
            ls += __shfl_xor_sync(0xffffffffu, ls, 2);
            l_[r] = l_[r] * fac + ls;
            m_[r] = mn;
            #pragma unroll
            for (int ni = 0; ni < 8; ni++) { acc[ni][r * 2] *= fac; acc[ni][r * 2 + 1] *= fac; }
        }

        #pragma unroll
        for (int kk = 0; kk < 4; kk++) {
            uint32_t a0 = *(uint32_t*)&ph[2 * kk][0];
            uint32_t a1 = *(uint32_t*)&ph[2 * kk][1];
            uint32_t a2 = *(uint32_t*)&ph[2 * kk + 1][0];
            uint32_t a3 = *(uint32_t*)&ph[2 * kk + 1][1];
            #pragma unroll
            for (int n2 = 0; n2 < 4; n2++) {
                uint32_t b0, b1, b2, b3;
                ldsm4t(b0, b1, b2, b3,
                       smem_u32(&Vs[st][kk * 16 + (lane & 15)][n2 * 16 + (lane >> 4) * 8]));
                mma16816(acc[n2 * 2],     a0, a1, a2, a3, b0, b1);
                mma16816(acc[n2 * 2 + 1], a0, a1, a2, a3, b2, b3);
            }
        }
    }

    float inv0 = 1.f / l_[0], inv1 = 1.f / l_[1];
    #pragma unroll
    for (int ni = 0; ni < 8; ni++) {
        int d = ni * 8 + (lane & 3) * 2;
        int t = t0 + w * 16 + (lane >> 2);
        *(__half2*)&Mg[(size_t)t * Cc + h * Dd + d] =
            __floats2half2_rn(acc[ni][0] * inv0, acc[ni][1] * inv0);
        *(__half2*)&Mg[(size_t)(t + 8) * Cc + h * Dd + d] =
            __floats2half2_rn(acc[ni][2] * inv1, acc[ni][3] * inv1);
    }
}

// ======================================================================
extern "C" void kernel_launch(void* const* d_in, const int* in_sizes, int n_in,
                              void* d_out, int out_size) {
    const float* x       = (const float*)d_in[0];
    const float* enc     = (const float*)d_in[1];
    const float* w_qkv   = (const float*)d_in[2];
    const float* w_proj  = (const float*)d_in[3];
    const float* b_proj  = (const float*)d_in[4];
    const float* cw_q    = (const float*)d_in[5];
    const float* cw_kv   = (const float*)d_in[6];
    const float* cw_proj = (const float*)d_in[7];
    const float* cb_proj = (const float*)d_in[8];
    const float* ff1_w1  = (const float*)d_in[9];
    const float* ff1_b1  = (const float*)d_in[10];
    const float* ff1_w2  = (const float*)d_in[11];
    const float* ff1_b2  = (const float*)d_in[12];
    const float* ff2_w1  = (const float*)d_in[13];
    const float* ff2_b1  = (const float*)d_in[14];
    const float* ff2_w2  = (const float*)d_in[15];
    const float* ff2_b2  = (const float*)d_in[16];
    const float* ln1_w = (const float*)d_in[17]; const float* ln1_b = (const float*)d_in[18];
    const float* ln2_w = (const float*)d_in[19]; const float* ln2_b = (const float*)d_in[20];
    const float* ln3_w = (const float*)d_in[21]; const float* ln3_b = (const float*)d_in[22];
    const float* ln4_w = (const float*)d_in[23]; const float* ln4_b = (const float*)d_in[24];

    float *px;
    __half *pln, *penc, *pwqkv, *pcwq, *pcwkv, *pwproj, *pcwproj;
    __half *pf11, *pf12, *pf21, *pf22;
    __half *py, *pcq, *pkv, *pm, *pff;
    cudaGetSymbolAddress((void**)&px,     g_x);
    cudaGetSymbolAddress((void**)&pln,    h_ln);
    cudaGetSymbolAddress((void**)&penc,   h_enc);
    cudaGetSymbolAddress((void**)&pwqkv,  h_wqkv);
    cudaGetSymbolAddress((void**)&pcwq,   h_cwq);
    cudaGetSymbolAddress((void**)&pcwkv,  h_cwkv);
    cudaGetSymbolAddress((void**)&pwproj, h_wproj);
    cudaGetSymbolAddress((void**)&pcwproj,h_cwproj);
    cudaGetSymbolAddress((void**)&pf11,   h_ff1w1);
    cudaGetSymbolAddress((void**)&pf12,   h_ff1w2);
    cudaGetSymbolAddress((void**)&pf21,   h_ff2w1);
    cudaGetSymbolAddress((void**)&pf22,   h_ff2w2);
    cudaGetSymbolAddress((void**)&py,     h_y);
    cudaGetSymbolAddress((void**)&pcq,    h_cq);
    cudaGetSymbolAddress((void**)&pkv,    h_kv);
    cudaGetSymbolAddress((void**)&pm,     h_m);
    cudaGetSymbolAddress((void**)&pff,    h_ff);

    cudaFuncSetAttribute(hgemm_kernel, cudaFuncAttributeMaxDynamicSharedMemorySize, HG_SMEM);
    cudaFuncSetAttribute(flash_kernel, cudaFuncAttributeMaxDynamicSharedMemorySize, FL_SMEM);

    auto cgrid = [](int n) { return (n + 255) / 256; };

    // ---- critical-path converts on the capture stream ----
    pack_w_kernel<<<cgrid(Hh*Cc*192/8), 256>>>(w_qkv, pwqkv, 192);
    cudaMemcpyAsync(px, x, (size_t)MM * Cc * sizeof(float), cudaMemcpyDeviceToDevice, 0);
    cudaEventRecord(g_ev1, 0);

    // ---- converts + cross-KV GEMM on side stream ----
    cudaStreamWaitEvent(g_s2, g_ev1, 0);
    pack_w_kernel<<<cgrid(Hh*Cc*64/8),  256, 0, g_s2>>>(cw_q,  pcwq,  64);
    pack_w_kernel<<<cgrid(Hh*Cc*128/8), 256, 0, g_s2>>>(cw_kv, pcwkv, 128);
    f2h_kernel<<<cgrid(Cc*Cc/4),  256, 0, g_s2>>>(w_proj,  pwproj,  Cc*Cc/4);
    f2h_kernel<<<cgrid(Cc*Cc/4),  256, 0, g_s2>>>(cw_proj, pcwproj, Cc*Cc/4);
    f2h_kernel<<<cgrid(Cc*FFF/4), 256, 0, g_s2>>>(ff1_w1, pf11, Cc*FFF/4);
    f2h_kernel<<<cgrid(FFF*Cc/4), 256, 0, g_s2>>>(ff1_w2, pf12, FFF*Cc/4);
    f2h_kernel<<<cgrid(Cc*FFF/4), 256, 0, g_s2>>>(ff2_w1, pf21, Cc*FFF/4);
    f2h_kernel<<<cgrid(FFF*Cc/4), 256, 0, g_s2>>>(ff2_w2, pf22, FFF*Cc/4);
    f2h_kernel<<<cgrid(MM*Cc/4),  256, 0, g_s2>>>(enc, penc, MM*Cc/4);
    cudaEventRecord(g_ev2, g_s2);            // weights ready
    hgemm_kernel<<<dim3(16, 32), 256, HG_SMEM, g_s2>>>(penc, pcwkv, nullptr, nullptr, nullptr, pkv, MM, 2048, Cc, 0);
    cudaEventRecord(g_ev3, g_s2);            // cross K/V ready

    // ---- per-batch pipelines on 4 streams ----
    auto run_batch = [&](int b, cudaStream_t st) {
        size_t oc = (size_t)b * Tt * Cc;
        float*  pxb  = px  + oc;
        __half* plnb = pln + oc;
        __half* pyb  = py  + (size_t)b * Tt * 3072;
        __half* pcqb = pcq + oc;
        __half* pkvb = pkv + (size_t)b * Tt * 2048;
        __half* pmb  = pm  + oc;
        __half* pffb = pff + (size_t)b * Tt * FFF;
        float*  poutb = (float*)d_out + oc;

        // 1) causal self-attention
        ln_kernel<<<Tt/8, 256, 0, st>>>(pxb, ln1_w, ln1_b, plnb);
        hgemm_kernel<<<dim3(24, 8), 256, HG_SMEM, st>>>(plnb, pwqkv, nullptr, nullptr, nullptr, pyb, Tt, 3072, Cc, 0);
        flash_kernel<<<dim3(8, Hh), 256, FL_SMEM, st>>>(pyb, pyb + 64, pyb + 128, pmb, 3072, 192, 3072, 192, 1);
        cudaStreamWaitEvent(st, g_ev2, 0);   // weights ready
        hgemm_kernel<<<dim3(8, 8), 256, HG_SMEM, st>>>(pmb, pwproj, b_proj, pxb, pxb, nullptr, Tt, Cc, Cc, 0);

        // 2) feed-forward 1
        ln_kernel<<<Tt/8, 256, 0, st>>>(pxb, ln2_w, ln2_b, plnb);
        hgemm_kernel<<<dim3(32, 8), 256, HG_SMEM, st>>>(plnb, pf11, ff1_b1, nullptr, nullptr, pffb, Tt, FFF, Cc, 1);
        hgemm_kernel<<<dim3(8, 8), 256, HG_SMEM, st>>>(pffb, pf12, ff1_b2, pxb, pxb, nullptr, Tt, Cc, FFF, 0);

        // 3) cross-attention
        ln_kernel<<<Tt/8, 256, 0, st>>>(pxb, ln3_w, ln3_b, plnb);
        hgemm_kernel<<<dim3(8, 8), 256, HG_SMEM, st>>>(plnb, pcwq, nullptr, nullptr, nullptr, pcqb, Tt, 1024, Cc, 0);
        cudaStreamWaitEvent(st, g_ev3, 0);   // cross K/V ready
        flash_kernel<<<dim3(8, Hh), 256, FL_SMEM, st>>>(pcqb, pkvb, pkvb + 64, pmb, 1024, 64, 2048, 128, 0);
        hgemm_kernel<<<dim3(8, 8), 256, HG_SMEM, st>>>(pmb, pcwproj, cb_proj, pxb, pxb, nullptr, Tt, Cc, Cc, 0);

        // 4) feed-forward 2 -> d_out
        ln_kernel<<<Tt/8, 256, 0, st>>>(pxb, ln4_w, ln4_b, plnb);
        hgemm_kernel<<<dim3(32, 8), 256, HG_SMEM, st>>>(plnb, pf21, ff2_b1, nullptr, nullptr, pffb, Tt, FFF, Cc, 1);
        hgemm_kernel<<<dim3(8, 8), 256, HG_SMEM, st>>>(pffb, pf22, ff2_b2, pxb, poutb, nullptr, Tt, Cc, FFF, 0);
    };

    // batch 0 on the capture stream; batches 1-3 on side streams
    for (int i = 0; i < 3; i++) cudaStreamWaitEvent(g_sb[i], g_ev1, 0);
    run_batch(0, 0);
    for (int i = 0; i < 3; i++) run_batch(i + 1, g_sb[i]);

    // ---- join everything back into the capture stream ----
    for (int i = 0; i < 3; i++) {
        cudaEventRecord(g_evb[i], g_sb[i]);
        cudaStreamWaitEvent(0, g_evb[i], 0);
    }
    cudaStreamWaitEvent(0, g_ev3, 0);        // join side stream s2 as well
}